// round 6
// baseline (speedup 1.0000x reference)
#include <cuda_runtime.h>
#include <cstdint>

#define EPS 1e-5f

// ---------------- scratch (device globals; allocation-free) ----------------
__device__ float g_u12red[32 * 1024];       // [r, ii]  sum over last axis of U12
__device__ float g_u3red [32 * 1024];       // [r, jj]  sum over last axis of U3R
__device__ float g_remb[64 * 32];           // BN(R[r_idx])
__device__ float g_e2  [64 * 32];           // BN(E[e2_idx])
__device__ float g_e3  [64 * 32];           // BN(E[e3_idx])
__device__ float g_p   [32];                // P.sum(-1)
__device__ float g_vec [64 * 32];           // vec (pre-BN)
__device__ float g_bsum[512 * 64];          // per-logit-block exp partial sums

static const int ENT = 50000;
static const int LOG_BLKS = (ENT + 127) / 128;   // 391 (128 entities per block)

// ---------------- K1: row reduction of U12 and U3R (the 256 MB stream) -----
__global__ void reduce_kernel(const float* __restrict__ U12,
                              const float* __restrict__ U3R)
{
    int gw   = (blockIdx.x * 256 + threadIdx.x) >> 5;   // global warp id, 65536 total
    int lane = threadIdx.x & 31;
    const float* src;
    float* dst;
    int row;
    if (gw < 32768) { src = U12; dst = g_u12red; row = gw; }
    else            { src = U3R; dst = g_u3red;  row = gw - 32768; }

    const float4* p = reinterpret_cast<const float4*>(src + (size_t)row * 1024) + lane;
    float4 a0 = p[0],   a1 = p[32],  a2 = p[64],  a3 = p[96];
    float4 a4 = p[128], a5 = p[160], a6 = p[192], a7 = p[224];
    float s = ((a0.x + a0.y) + (a0.z + a0.w)) + ((a1.x + a1.y) + (a1.z + a1.w))
            + ((a2.x + a2.y) + (a2.z + a2.w)) + ((a3.x + a3.y) + (a3.z + a3.w))
            + ((a4.x + a4.y) + (a4.z + a4.w)) + ((a5.x + a5.y) + (a5.z + a5.w))
            + ((a6.x + a6.y) + (a6.z + a6.w)) + ((a7.x + a7.y) + (a7.z + a7.w));
    #pragma unroll
    for (int off = 16; off; off >>= 1)
        s += __shfl_down_sync(0xffffffffu, s, off);
    if (lane == 0) dst[row] = s;
}

// ---------------- K2: gathers + 3 BatchNorms (3 concurrent warps) ----------
__global__ void prep_kernel(const float* __restrict__ E,
                            const float* __restrict__ R,
                            const float* __restrict__ P,
                            const float* __restrict__ gr, const float* __restrict__ br,
                            const float* __restrict__ ge, const float* __restrict__ be,
                            const int* __restrict__ r_idx,
                            const int* __restrict__ e2_idx,
                            const int* __restrict__ e3_idx)
{
    __shared__ float shr[2048], sh2[2048], sh3[2048];
    __shared__ int ridx[64], e2i[64], e3i[64];
    int t = threadIdx.x;                     // 256 threads
    if (t < 64)            ridx[t]       = r_idx[t];
    else if (t < 128)      e2i[t - 64]   = e2_idx[t - 64];
    else if (t < 192)      e3i[t - 128]  = e3_idx[t - 128];
    __syncthreads();

    for (int i = t; i < 2048; i += 256) {
        int b = i >> 5, d = i & 31;
        shr[i] = R[(size_t)ridx[b] * 32 + d];
        sh2[i] = E[(size_t)e2i[b] * 32 + d];
        sh3[i] = E[(size_t)e3i[b] * 32 + d];
    }
    if (t >= 224) {                          // last warp: p[r] = P.sum(-1)
        int r = t - 224;
        const float4* row = reinterpret_cast<const float4*>(P + r * 32);
        float s = 0.f;
        #pragma unroll
        for (int q = 0; q < 8; q++) { float4 v = row[q]; s += (v.x+v.y)+(v.z+v.w); }
        g_p[r] = s;
    }
    __syncthreads();

    int w = t >> 5, l = t & 31;
    if (w < 3) {                             // warp w does BN #w
        const float* sh  = (w == 0) ? shr : (w == 1) ? sh2 : sh3;
        const float* gg  = (w == 0) ? gr  : ge;
        const float* bb  = (w == 0) ? br  : be;
        float* dst       = (w == 0) ? g_remb : (w == 1) ? g_e2 : g_e3;
        float m = 0.f;
        #pragma unroll 8
        for (int b = 0; b < 64; b++) m += sh[b * 32 + l];
        m *= (1.f / 64.f);
        float v = 0.f;
        #pragma unroll 8
        for (int b = 0; b < 64; b++) { float d = sh[b * 32 + l] - m; v += d * d; }
        v *= (1.f / 64.f);
        float sc = gg[l] * rsqrtf(v + EPS);
        float of = bb[l] - m * sc;
        #pragma unroll 8
        for (int b = 0; b < 64; b++) dst[b * 32 + l] = sh[b * 32 + l] * sc + of;
    }
}

// ---------------- K3: per-batch contraction (64 blocks, 1 per b) -----------
__global__ void contract_kernel(const float* __restrict__ U_root,
                                const int* __restrict__ r_idx,
                                const int* __restrict__ miss_p)
{
    int b = blockIdx.x, t = threadIdx.x;
    int wid = t >> 5, lane = t & 31;
    int miss = miss_p ? *miss_p : 3;

    __shared__ float A1s[32], A2s[32], Vs[32];
    __shared__ float m[1024];                // outer product A1⊗A2
    __shared__ float y[1024];                // coef[r]*V[j]
    __shared__ float afr[32];                // a[b][r] = U_root[ridx[b]][r].sum()
    __shared__ float coef[32];
    __shared__ float partial[8][32];

    // gather + rowsum of U_root[ridx[b]] : thread t handles (r = t>>3, seg = t&7)
    {
        int ridx = r_idx[b];
        const float4* seg = reinterpret_cast<const float4*>(
            U_root + ((size_t)ridx * 32 + (t >> 3)) * 32) + (t & 7);
        float4 v = *seg;
        float s = (v.x + v.y) + (v.z + v.w);
        s += __shfl_down_sync(0xffffffffu, s, 4, 8);
        s += __shfl_down_sync(0xffffffffu, s, 2, 8);
        s += __shfl_down_sync(0xffffffffu, s, 1, 8);
        if ((t & 7) == 0) afr[t >> 3] = s;
    }

    if (t < 32) {
        if (miss == 1) { A1s[t] = g_e2[b*32+t];  A2s[t] = g_e3[b*32+t]; Vs[t] = g_remb[b*32+t]; }
        else           { A1s[t] = g_remb[b*32+t]; A2s[t] = g_e2[b*32+t]; Vs[t] = g_e3[b*32+t]; }
    }
    __syncthreads();
    for (int i = t; i < 1024; i += 256) m[i] = A1s[i >> 5] * A2s[i & 31];
    __syncthreads();

    const float* SU = (miss == 1) ? g_u3red  : g_u12red;   // scalar side
    const float* TU = (miss == 1) ? g_u12red : g_u3red;    // vector side

    // coef[r] = (Σ_ii SU[r,ii]*m[ii]) * a[b,r] * p[r]; warp wid owns r in [4w,4w+4)
    #pragma unroll
    for (int rr = 0; rr < 4; rr++) {
        int r = wid * 4 + rr;
        const float4* row = reinterpret_cast<const float4*>(SU + (size_t)r * 1024);
        float s = 0.f;
        #pragma unroll
        for (int q = 0; q < 8; q++) {
            float4 u = row[q * 32 + lane];
            const float4 mm = reinterpret_cast<const float4*>(m)[q * 32 + lane];
            s += u.x * mm.x + u.y * mm.y + u.z * mm.z + u.w * mm.w;
        }
        #pragma unroll
        for (int off = 16; off; off >>= 1)
            s += __shfl_down_sync(0xffffffffu, s, off);
        if (lane == 0) coef[r] = s * afr[r] * g_p[r];
    }
    __syncthreads();
    for (int i = t; i < 1024; i += 256) y[i] = coef[i >> 5] * Vs[i & 31];
    __syncthreads();

    // output: thread (k=t&31, part=t>>5); part owns r in [4p,4p+4)
    int k = t & 31, part = t >> 5;
    float acc = 0.f;
    if (miss == 2) {
        #pragma unroll
        for (int rr = 0; rr < 4; rr++) {
            int r = part * 4 + rr;
            const float4* seg = reinterpret_cast<const float4*>(TU + (size_t)r * 1024 + k * 32);
            #pragma unroll
            for (int q = 0; q < 8; q++) {
                float4 u = seg[q];
                acc += u.x * y[r*32 + q*4]   + u.y * y[r*32 + q*4+1]
                     + u.z * y[r*32 + q*4+2] + u.w * y[r*32 + q*4+3];
            }
        }
    } else {
        #pragma unroll
        for (int rr = 0; rr < 4; rr++) {
            int r = part * 4 + rr;
            #pragma unroll
            for (int j = 0; j < 32; j++)
                acc += y[r * 32 + j] * TU[(size_t)r * 1024 + j * 32 + k];
        }
    }
    partial[part][k] = acc;
    __syncthreads();
    if (t < 32) {
        float s = 0.f;
        #pragma unroll
        for (int p8 = 0; p8 < 8; p8++) s += partial[p8][t];
        g_vec[b * 32 + t] = s;
    }
}

// ---------------- K4: logits + exp + per-block sums (BN(vec) inline) -------
// Block: 256 threads = 64 entity-slots x 4 b-groups; each thread does
// 2 entities x 16 batch rows. Grid 391 -> ~2.6 waves, high ILP.
__global__ void logits_kernel(const float* __restrict__ E,
                              const float* __restrict__ gw,
                              const float* __restrict__ bw,
                              float* __restrict__ out)
{
    __shared__ float4 vecn4[512];            // BN'd vec, [b][8] float4
    __shared__ float  vraw[2048];
    __shared__ float  sc_s[32], of_s[32];
    __shared__ float  wsum[64][8];
    int t = threadIdx.x;
    for (int i = t; i < 2048; i += 256) vraw[i] = g_vec[i];
    __syncthreads();
    if (t < 32) {                            // per-feature BN stats (redundant per block)
        float m = 0.f;
        #pragma unroll 8
        for (int b = 0; b < 64; b++) m += vraw[b * 32 + t];
        m *= (1.f / 64.f);
        float v = 0.f;
        #pragma unroll 8
        for (int b = 0; b < 64; b++) { float d = vraw[b * 32 + t] - m; v += d * d; }
        v *= (1.f / 64.f);
        float sc = gw[t] * rsqrtf(v + EPS);
        sc_s[t] = sc;
        of_s[t] = bw[t] - m * sc;
    }
    __syncthreads();
    {
        float* vecnf = reinterpret_cast<float*>(vecn4);
        for (int i = t; i < 2048; i += 256)
            vecnf[i] = vraw[i] * sc_s[i & 31] + of_s[i & 31];
    }
    __syncthreads();

    int el = t & 63, bgrp = t >> 6;          // entity slot, b-group
    int n0 = blockIdx.x * 128 + el;
    int n1 = n0 + 64;
    bool v0 = n0 < ENT, v1 = n1 < ENT;
    float4 er0[8], er1[8];
    if (v0) {
        const float4* p = reinterpret_cast<const float4*>(E + (size_t)n0 * 32);
        #pragma unroll
        for (int q = 0; q < 8; q++) er0[q] = p[q];
    } else {
        #pragma unroll
        for (int q = 0; q < 8; q++) er0[q] = make_float4(0.f,0.f,0.f,0.f);
    }
    if (v1) {
        const float4* p = reinterpret_cast<const float4*>(E + (size_t)n1 * 32);
        #pragma unroll
        for (int q = 0; q < 8; q++) er1[q] = p[q];
    } else {
        #pragma unroll
        for (int q = 0; q < 8; q++) er1[q] = make_float4(0.f,0.f,0.f,0.f);
    }

    int wid = t >> 5, lane = t & 31;
    int b0 = bgrp * 16;
    for (int bb = 0; bb < 16; bb += 4) {
        int b = b0 + bb;
        float l00=0.f,l01=0.f,l10=0.f,l11=0.f,l20=0.f,l21=0.f,l30=0.f,l31=0.f;
        #pragma unroll
        for (int q = 0; q < 8; q++) {
            float4 e0 = er0[q], e1 = er1[q];
            float4 w0 = vecn4[(b+0)*8 + q];
            float4 w1 = vecn4[(b+1)*8 + q];
            float4 w2 = vecn4[(b+2)*8 + q];
            float4 w3 = vecn4[(b+3)*8 + q];
            l00 += w0.x*e0.x + w0.y*e0.y + w0.z*e0.z + w0.w*e0.w;
            l01 += w0.x*e1.x + w0.y*e1.y + w0.z*e1.z + w0.w*e1.w;
            l10 += w1.x*e0.x + w1.y*e0.y + w1.z*e0.z + w1.w*e0.w;
            l11 += w1.x*e1.x + w1.y*e1.y + w1.z*e1.z + w1.w*e1.w;
            l20 += w2.x*e0.x + w2.y*e0.y + w2.z*e0.z + w2.w*e0.w;
            l21 += w2.x*e1.x + w2.y*e1.y + w2.z*e1.z + w2.w*e1.w;
            l30 += w3.x*e0.x + w3.y*e0.y + w3.z*e0.z + w3.w*e0.w;
            l31 += w3.x*e1.x + w3.y*e1.y + w3.z*e1.z + w3.w*e1.w;
        }
        float p00 = v0 ? __expf(l00) : 0.f;
        float p01 = v1 ? __expf(l01) : 0.f;
        float p10 = v0 ? __expf(l10) : 0.f;
        float p11 = v1 ? __expf(l11) : 0.f;
        float p20 = v0 ? __expf(l20) : 0.f;
        float p21 = v1 ? __expf(l21) : 0.f;
        float p30 = v0 ? __expf(l30) : 0.f;
        float p31 = v1 ? __expf(l31) : 0.f;
        if (v0) {
            out[(size_t)(b+0)*ENT + n0] = p00;
            out[(size_t)(b+1)*ENT + n0] = p10;
            out[(size_t)(b+2)*ENT + n0] = p20;
            out[(size_t)(b+3)*ENT + n0] = p30;
        }
        if (v1) {
            out[(size_t)(b+0)*ENT + n1] = p01;
            out[(size_t)(b+1)*ENT + n1] = p11;
            out[(size_t)(b+2)*ENT + n1] = p21;
            out[(size_t)(b+3)*ENT + n1] = p31;
        }
        float s0 = p00 + p01, s1 = p10 + p11, s2 = p20 + p21, s3 = p30 + p31;
        #pragma unroll
        for (int off = 16; off; off >>= 1) {
            s0 += __shfl_down_sync(0xffffffffu, s0, off);
            s1 += __shfl_down_sync(0xffffffffu, s1, off);
            s2 += __shfl_down_sync(0xffffffffu, s2, off);
            s3 += __shfl_down_sync(0xffffffffu, s3, off);
        }
        if (lane == 0) {
            wsum[b+0][wid] = s0; wsum[b+1][wid] = s1;
            wsum[b+2][wid] = s2; wsum[b+3][wid] = s3;
        }
    }
    __syncthreads();
    if (t < 64) {
        int w2 = (t >> 4) * 2;               // the two warps that own b-group t>>4
        g_bsum[blockIdx.x * 64 + t] = wsum[t][w2] + wsum[t][w2 + 1];
    }
}

// ---------------- K5: normalize (denominator reduced inline per block) -----
__global__ void norm_kernel(float* __restrict__ out, int nblk)
{
    __shared__ float red[256];
    int b = blockIdx.y, t = threadIdx.x;
    float s = 0.f;
    for (int q = t; q < nblk; q += 256) s += g_bsum[q * 64 + b];
    red[t] = s;
    __syncthreads();
    #pragma unroll
    for (int off = 128; off; off >>= 1) {
        if (t < off) red[t] += red[t + off];
        __syncthreads();
    }
    float inv = 1.f / red[0];

    int i = blockIdx.x * 256 + t;            // float4 index within row (12500 per row)
    if (i < 12500) {
        float4* p = reinterpret_cast<float4*>(out + (size_t)b * ENT);
        float4 v = p[i];
        v.x *= inv; v.y *= inv; v.z *= inv; v.w *= inv;
        p[i] = v;
    }
}

// ---------------- launch ----------------------------------------------------
extern "C" void kernel_launch(void* const* d_in, const int* in_sizes, int n_in,
                              void* d_out, int out_size)
{
    const float* E      = (const float*)d_in[0];
    const float* R      = (const float*)d_in[1];
    const float* U_root = (const float*)d_in[2];
    const float* U12    = (const float*)d_in[3];
    const float* U3R    = (const float*)d_in[4];
    const float* P      = (const float*)d_in[5];
    const float* gr     = (const float*)d_in[6];
    const float* br     = (const float*)d_in[7];
    const float* ge     = (const float*)d_in[8];
    const float* be     = (const float*)d_in[9];
    const float* gw     = (const float*)d_in[10];
    const float* bw     = (const float*)d_in[11];
    const int* r_idx    = (const int*)d_in[12];
    const int* e2_idx   = (const int*)d_in[13];
    const int* e3_idx   = (const int*)d_in[14];
    const int* miss     = (n_in > 15) ? (const int*)d_in[15] : nullptr;
    float* out = (float*)d_out;

    reduce_kernel<<<8192, 256>>>(U12, U3R);
    prep_kernel<<<1, 256>>>(E, R, P, gr, br, ge, be, r_idx, e2_idx, e3_idx);
    contract_kernel<<<64, 256>>>(U_root, r_idx, miss);
    logits_kernel<<<LOG_BLKS, 256>>>(E, gw, bw, out);
    norm_kernel<<<dim3((12500 + 255) / 256, 64), 256>>>(out, LOG_BLKS);
}

// round 7
// speedup vs baseline: 1.0155x; 1.0155x over previous
#include <cuda_runtime.h>
#include <cstdint>

#define EPS 1e-5f

// ---------------- scratch (device globals; allocation-free) ----------------
__device__ float g_u12red[32 * 1024];       // [r, ii]  sum over last axis of U12
__device__ float g_u3red [32 * 1024];       // [r, jj]  sum over last axis of U3R
__device__ float g_remb[64 * 32];           // BN(R[r_idx])
__device__ float g_e2  [64 * 32];           // BN(E[e2_idx])
__device__ float g_e3  [64 * 32];           // BN(E[e3_idx])
__device__ float g_p   [32];                // P.sum(-1)
__device__ float g_vec [64 * 32];           // vec (pre-BN)
__device__ float g_vecn[64 * 32];           // BN(vec)
__device__ float g_bsum[512 * 64];          // per-logit-block exp partial sums

static const int ENT = 50000;
static const int LOG_BLKS = (ENT + 127) / 128;   // 391 (128 entities per block)

// ---------------- K1: row reduction of U12 and U3R (the 256 MB stream) -----
__global__ void reduce_kernel(const float* __restrict__ U12,
                              const float* __restrict__ U3R)
{
    int gw   = (blockIdx.x * 256 + threadIdx.x) >> 5;   // global warp id, 65536 total
    int lane = threadIdx.x & 31;
    const float* src;
    float* dst;
    int row;
    if (gw < 32768) { src = U12; dst = g_u12red; row = gw; }
    else            { src = U3R; dst = g_u3red;  row = gw - 32768; }

    const float4* p = reinterpret_cast<const float4*>(src + (size_t)row * 1024) + lane;
    float4 a0 = p[0],   a1 = p[32],  a2 = p[64],  a3 = p[96];
    float4 a4 = p[128], a5 = p[160], a6 = p[192], a7 = p[224];
    float s = ((a0.x + a0.y) + (a0.z + a0.w)) + ((a1.x + a1.y) + (a1.z + a1.w))
            + ((a2.x + a2.y) + (a2.z + a2.w)) + ((a3.x + a3.y) + (a3.z + a3.w))
            + ((a4.x + a4.y) + (a4.z + a4.w)) + ((a5.x + a5.y) + (a5.z + a5.w))
            + ((a6.x + a6.y) + (a6.z + a6.w)) + ((a7.x + a7.y) + (a7.z + a7.w));
    #pragma unroll
    for (int off = 16; off; off >>= 1)
        s += __shfl_down_sync(0xffffffffu, s, off);
    if (lane == 0) dst[row] = s;
}

// ---------------- K2: gathers + 3 BatchNorms (3 concurrent warps) ----------
__global__ void prep_kernel(const float* __restrict__ E,
                            const float* __restrict__ R,
                            const float* __restrict__ P,
                            const float* __restrict__ gr, const float* __restrict__ br,
                            const float* __restrict__ ge, const float* __restrict__ be,
                            const int* __restrict__ r_idx,
                            const int* __restrict__ e2_idx,
                            const int* __restrict__ e3_idx)
{
    __shared__ float shr[2048], sh2[2048], sh3[2048];
    __shared__ int ridx[64], e2i[64], e3i[64];
    int t = threadIdx.x;                     // 256 threads
    if (t < 64)            ridx[t]       = r_idx[t];
    else if (t < 128)      e2i[t - 64]   = e2_idx[t - 64];
    else if (t < 192)      e3i[t - 128]  = e3_idx[t - 128];
    __syncthreads();

    for (int i = t; i < 2048; i += 256) {
        int b = i >> 5, d = i & 31;
        shr[i] = R[(size_t)ridx[b] * 32 + d];
        sh2[i] = E[(size_t)e2i[b] * 32 + d];
        sh3[i] = E[(size_t)e3i[b] * 32 + d];
    }
    if (t >= 224) {                          // last warp: p[r] = P.sum(-1)
        int r = t - 224;
        const float4* row = reinterpret_cast<const float4*>(P + r * 32);
        float s = 0.f;
        #pragma unroll
        for (int q = 0; q < 8; q++) { float4 v = row[q]; s += (v.x+v.y)+(v.z+v.w); }
        g_p[r] = s;
    }
    __syncthreads();

    int w = t >> 5, l = t & 31;
    if (w < 3) {                             // warp w does BN #w
        const float* sh  = (w == 0) ? shr : (w == 1) ? sh2 : sh3;
        const float* gg  = (w == 0) ? gr  : ge;
        const float* bb  = (w == 0) ? br  : be;
        float* dst       = (w == 0) ? g_remb : (w == 1) ? g_e2 : g_e3;
        float m = 0.f;
        #pragma unroll 8
        for (int b = 0; b < 64; b++) m += sh[b * 32 + l];
        m *= (1.f / 64.f);
        float v = 0.f;
        #pragma unroll 8
        for (int b = 0; b < 64; b++) { float d = sh[b * 32 + l] - m; v += d * d; }
        v *= (1.f / 64.f);
        float sc = gg[l] * rsqrtf(v + EPS);
        float of = bb[l] - m * sc;
        #pragma unroll 8
        for (int b = 0; b < 64; b++) dst[b * 32 + l] = sh[b * 32 + l] * sc + of;
    }
}

// ---------------- K3: per-batch contraction (64 blocks, 1 per b) -----------
__global__ void contract_kernel(const float* __restrict__ U_root,
                                const int* __restrict__ r_idx,
                                const int* __restrict__ miss_p)
{
    int b = blockIdx.x, t = threadIdx.x;
    int wid = t >> 5, lane = t & 31;
    int miss = miss_p ? *miss_p : 3;

    __shared__ float A1s[32], A2s[32], Vs[32];
    __shared__ float m[1024];                // outer product A1⊗A2
    __shared__ float y[1024];                // coef[r]*V[j]
    __shared__ float afr[32];                // a[b][r] = U_root[ridx[b]][r].sum()
    __shared__ float coef[32];
    __shared__ float partial[8][32];

    // gather + rowsum of U_root[ridx[b]] : thread t handles (r = t>>3, seg = t&7)
    {
        int ridx = r_idx[b];
        const float4* seg = reinterpret_cast<const float4*>(
            U_root + ((size_t)ridx * 32 + (t >> 3)) * 32) + (t & 7);
        float4 v = *seg;
        float s = (v.x + v.y) + (v.z + v.w);
        s += __shfl_down_sync(0xffffffffu, s, 4, 8);
        s += __shfl_down_sync(0xffffffffu, s, 2, 8);
        s += __shfl_down_sync(0xffffffffu, s, 1, 8);
        if ((t & 7) == 0) afr[t >> 3] = s;
    }

    if (t < 32) {
        if (miss == 1) { A1s[t] = g_e2[b*32+t];  A2s[t] = g_e3[b*32+t]; Vs[t] = g_remb[b*32+t]; }
        else           { A1s[t] = g_remb[b*32+t]; A2s[t] = g_e2[b*32+t]; Vs[t] = g_e3[b*32+t]; }
    }
    __syncthreads();
    for (int i = t; i < 1024; i += 256) m[i] = A1s[i >> 5] * A2s[i & 31];
    __syncthreads();

    const float* SU = (miss == 1) ? g_u3red  : g_u12red;   // scalar side
    const float* TU = (miss == 1) ? g_u12red : g_u3red;    // vector side

    // coef[r] = (Σ_ii SU[r,ii]*m[ii]) * a[b,r] * p[r]; warp wid owns r in [4w,4w+4)
    #pragma unroll
    for (int rr = 0; rr < 4; rr++) {
        int r = wid * 4 + rr;
        const float4* row = reinterpret_cast<const float4*>(SU + (size_t)r * 1024);
        float s = 0.f;
        #pragma unroll
        for (int q = 0; q < 8; q++) {
            float4 u = row[q * 32 + lane];
            const float4 mm = reinterpret_cast<const float4*>(m)[q * 32 + lane];
            s += u.x * mm.x + u.y * mm.y + u.z * mm.z + u.w * mm.w;
        }
        #pragma unroll
        for (int off = 16; off; off >>= 1)
            s += __shfl_down_sync(0xffffffffu, s, off);
        if (lane == 0) coef[r] = s * afr[r] * g_p[r];
    }
    __syncthreads();
    for (int i = t; i < 1024; i += 256) y[i] = coef[i >> 5] * Vs[i & 31];
    __syncthreads();

    // output: thread (k=t&31, part=t>>5); part owns r in [4p,4p+4)
    int k = t & 31, part = t >> 5;
    float acc = 0.f;
    if (miss == 2) {
        #pragma unroll
        for (int rr = 0; rr < 4; rr++) {
            int r = part * 4 + rr;
            const float4* seg = reinterpret_cast<const float4*>(TU + (size_t)r * 1024 + k * 32);
            #pragma unroll
            for (int q = 0; q < 8; q++) {
                float4 u = seg[q];
                acc += u.x * y[r*32 + q*4]   + u.y * y[r*32 + q*4+1]
                     + u.z * y[r*32 + q*4+2] + u.w * y[r*32 + q*4+3];
            }
        }
    } else {
        #pragma unroll
        for (int rr = 0; rr < 4; rr++) {
            int r = part * 4 + rr;
            #pragma unroll
            for (int j = 0; j < 32; j++)
                acc += y[r * 32 + j] * TU[(size_t)r * 1024 + j * 32 + k];
        }
    }
    partial[part][k] = acc;
    __syncthreads();
    if (t < 32) {
        float s = 0.f;
        #pragma unroll
        for (int p8 = 0; p8 < 8; p8++) s += partial[p8][t];
        g_vec[b * 32 + t] = s;
    }
}

// ---------------- K3b: BN(vec) -> g_vecn (1 warp) ---------------------------
__global__ void bnvec_kernel(const float* __restrict__ gw, const float* __restrict__ bw)
{
    int t = threadIdx.x;                     // 32 threads, feature t
    float v[64];
    float m = 0.f;
    #pragma unroll 8
    for (int b = 0; b < 64; b++) { v[b] = g_vec[b * 32 + t]; m += v[b]; }
    m *= (1.f / 64.f);
    float var = 0.f;
    #pragma unroll 8
    for (int b = 0; b < 64; b++) { float d = v[b] - m; var += d * d; }
    var *= (1.f / 64.f);
    float sc = gw[t] * rsqrtf(var + EPS);
    float of = bw[t] - m * sc;
    #pragma unroll 8
    for (int b = 0; b < 64; b++) g_vecn[b * 32 + t] = v[b] * sc + of;
}

// ---------------- K4: logits + exp + per-block sums -------------------------
// Grid (391, 2), block 128. blockIdx.y selects a 32-row b-half; each thread
// owns ONE entity (er in 32 regs) and loops over 32 b's in chunks of 4.
__global__ void logits_kernel(const float* __restrict__ E, float* __restrict__ out)
{
    __shared__ float4 vecn4[256];            // this half's BN'd vec: [32 b][8 q]
    __shared__ float  wsum[32][4];
    int t = threadIdx.x;                     // 128
    int bhalf = blockIdx.y;                  // 0 or 1
    {
        const float4* src = reinterpret_cast<const float4*>(g_vecn) + bhalf * 256;
        for (int i = t; i < 256; i += 128) vecn4[i] = src[i];
    }
    __syncthreads();

    int n = blockIdx.x * 128 + t;
    bool valid = n < ENT;
    float4 er[8];
    if (valid) {
        const float4* p = reinterpret_cast<const float4*>(E + (size_t)n * 32);
        #pragma unroll
        for (int q = 0; q < 8; q++) er[q] = p[q];
    } else {
        #pragma unroll
        for (int q = 0; q < 8; q++) er[q] = make_float4(0.f, 0.f, 0.f, 0.f);
    }

    int wid = t >> 5, lane = t & 31;
    size_t outbase = (size_t)(bhalf * 32) * ENT + n;

    #pragma unroll
    for (int c = 0; c < 8; c++) {            // 8 chunks of 4 b's
        int bl = c * 4;
        float l0 = 0.f, l1 = 0.f, l2 = 0.f, l3 = 0.f;
        #pragma unroll
        for (int q = 0; q < 8; q++) {
            float4 e  = er[q];
            float4 w0 = vecn4[(bl + 0) * 8 + q];
            float4 w1 = vecn4[(bl + 1) * 8 + q];
            float4 w2 = vecn4[(bl + 2) * 8 + q];
            float4 w3 = vecn4[(bl + 3) * 8 + q];
            l0 += w0.x*e.x + w0.y*e.y + w0.z*e.z + w0.w*e.w;
            l1 += w1.x*e.x + w1.y*e.y + w1.z*e.z + w1.w*e.w;
            l2 += w2.x*e.x + w2.y*e.y + w2.z*e.z + w2.w*e.w;
            l3 += w3.x*e.x + w3.y*e.y + w3.z*e.z + w3.w*e.w;
        }
        float p0 = valid ? __expf(l0) : 0.f;
        float p1 = valid ? __expf(l1) : 0.f;
        float p2 = valid ? __expf(l2) : 0.f;
        float p3 = valid ? __expf(l3) : 0.f;
        if (valid) {
            out[outbase + (size_t)(bl + 0) * ENT] = p0;
            out[outbase + (size_t)(bl + 1) * ENT] = p1;
            out[outbase + (size_t)(bl + 2) * ENT] = p2;
            out[outbase + (size_t)(bl + 3) * ENT] = p3;
        }
        #pragma unroll
        for (int off = 16; off; off >>= 1) {
            p0 += __shfl_down_sync(0xffffffffu, p0, off);
            p1 += __shfl_down_sync(0xffffffffu, p1, off);
            p2 += __shfl_down_sync(0xffffffffu, p2, off);
            p3 += __shfl_down_sync(0xffffffffu, p3, off);
        }
        if (lane == 0) {
            wsum[bl + 0][wid] = p0; wsum[bl + 1][wid] = p1;
            wsum[bl + 2][wid] = p2; wsum[bl + 3][wid] = p3;
        }
    }
    __syncthreads();
    if (t < 32)
        g_bsum[blockIdx.x * 64 + bhalf * 32 + t] =
            (wsum[t][0] + wsum[t][1]) + (wsum[t][2] + wsum[t][3]);
}

// ---------------- K5: normalize (denominator reduced inline per block) -----
__global__ void norm_kernel(float* __restrict__ out, int nblk)
{
    __shared__ float red[256];
    int b = blockIdx.y, t = threadIdx.x;
    float s = 0.f;
    for (int q = t; q < nblk; q += 256) s += g_bsum[q * 64 + b];
    red[t] = s;
    __syncthreads();
    #pragma unroll
    for (int off = 128; off; off >>= 1) {
        if (t < off) red[t] += red[t + off];
        __syncthreads();
    }
    float inv = 1.f / red[0];

    int i = blockIdx.x * 256 + t;            // float4 index within row (12500 per row)
    if (i < 12500) {
        float4* p = reinterpret_cast<float4*>(out + (size_t)b * ENT);
        float4 v = p[i];
        v.x *= inv; v.y *= inv; v.z *= inv; v.w *= inv;
        p[i] = v;
    }
}

// ---------------- launch ----------------------------------------------------
extern "C" void kernel_launch(void* const* d_in, const int* in_sizes, int n_in,
                              void* d_out, int out_size)
{
    const float* E      = (const float*)d_in[0];
    const float* R      = (const float*)d_in[1];
    const float* U_root = (const float*)d_in[2];
    const float* U12    = (const float*)d_in[3];
    const float* U3R    = (const float*)d_in[4];
    const float* P      = (const float*)d_in[5];
    const float* gr     = (const float*)d_in[6];
    const float* br     = (const float*)d_in[7];
    const float* ge     = (const float*)d_in[8];
    const float* be     = (const float*)d_in[9];
    const float* gw     = (const float*)d_in[10];
    const float* bw     = (const float*)d_in[11];
    const int* r_idx    = (const int*)d_in[12];
    const int* e2_idx   = (const int*)d_in[13];
    const int* e3_idx   = (const int*)d_in[14];
    const int* miss     = (n_in > 15) ? (const int*)d_in[15] : nullptr;
    float* out = (float*)d_out;

    reduce_kernel<<<8192, 256>>>(U12, U3R);
    prep_kernel<<<1, 256>>>(E, R, P, gr, br, ge, be, r_idx, e2_idx, e3_idx);
    contract_kernel<<<64, 256>>>(U_root, r_idx, miss);
    bnvec_kernel<<<1, 32>>>(gw, bw);
    logits_kernel<<<dim3(LOG_BLKS, 2), 128>>>(E, out);
    norm_kernel<<<dim3((12500 + 255) / 256, 64), 256>>>(out, LOG_BLKS);
}

// round 8
// speedup vs baseline: 1.0171x; 1.0016x over previous
#include <cuda_runtime.h>
#include <cstdint>

#define EPS 1e-5f

// ---------------- scratch (device globals; allocation-free) ----------------
__device__ float g_u12red[32 * 1024];       // [r, ii]  sum over last axis of U12
__device__ float g_u3red [32 * 1024];       // [r, jj]  sum over last axis of U3R
__device__ float g_remb[64 * 32];           // BN(R[r_idx])
__device__ float g_e2  [64 * 32];           // BN(E[e2_idx])
__device__ float g_e3  [64 * 32];           // BN(E[e3_idx])
__device__ float g_p   [32];                // P.sum(-1)
__device__ float g_vec [64 * 32];           // vec (pre-BN)
__device__ float g_vecn[64 * 32];           // BN(vec)
__device__ float g_bsum[512 * 64];          // per-logit-block exp partial sums

static const int ENT = 50000;
static const int LOG_BLKS = (ENT + 127) / 128;   // 391 (128 entities per block)

// exp(x) for small |x| via degree-6 Taylor (pure FFMA, no MUFU).
// Logits here are |x| <~ 0.04 by construction; fallback for safety.
__device__ __forceinline__ float exp_small(float x)
{
    if (fabsf(x) > 0.6f) return __expf(x);   // never taken in practice
    float p = 1.388888889e-3f;               // 1/720
    p = fmaf(p, x, 8.333333333e-3f);         // 1/120
    p = fmaf(p, x, 4.166666667e-2f);         // 1/24
    p = fmaf(p, x, 1.666666667e-1f);         // 1/6
    p = fmaf(p, x, 0.5f);
    p = fmaf(p, x, 1.0f);
    p = fmaf(p, x, 1.0f);
    return p;
}

// ---------------- K1: row reduction of U12 and U3R (the 256 MB stream) -----
__global__ void reduce_kernel(const float* __restrict__ U12,
                              const float* __restrict__ U3R)
{
    int gw   = (blockIdx.x * 256 + threadIdx.x) >> 5;   // global warp id, 65536 total
    int lane = threadIdx.x & 31;
    const float* src;
    float* dst;
    int row;
    if (gw < 32768) { src = U12; dst = g_u12red; row = gw; }
    else            { src = U3R; dst = g_u3red;  row = gw - 32768; }

    const float4* p = reinterpret_cast<const float4*>(src + (size_t)row * 1024) + lane;
    float4 a0 = p[0],   a1 = p[32],  a2 = p[64],  a3 = p[96];
    float4 a4 = p[128], a5 = p[160], a6 = p[192], a7 = p[224];
    float s = ((a0.x + a0.y) + (a0.z + a0.w)) + ((a1.x + a1.y) + (a1.z + a1.w))
            + ((a2.x + a2.y) + (a2.z + a2.w)) + ((a3.x + a3.y) + (a3.z + a3.w))
            + ((a4.x + a4.y) + (a4.z + a4.w)) + ((a5.x + a5.y) + (a5.z + a5.w))
            + ((a6.x + a6.y) + (a6.z + a6.w)) + ((a7.x + a7.y) + (a7.z + a7.w));
    #pragma unroll
    for (int off = 16; off; off >>= 1)
        s += __shfl_down_sync(0xffffffffu, s, off);
    if (lane == 0) dst[row] = s;
}

// ---------------- K2: gathers + 3 BatchNorms (3 concurrent warps) ----------
__global__ void prep_kernel(const float* __restrict__ E,
                            const float* __restrict__ R,
                            const float* __restrict__ P,
                            const float* __restrict__ gr, const float* __restrict__ br,
                            const float* __restrict__ ge, const float* __restrict__ be,
                            const int* __restrict__ r_idx,
                            const int* __restrict__ e2_idx,
                            const int* __restrict__ e3_idx)
{
    __shared__ float shr[2048], sh2[2048], sh3[2048];
    __shared__ int ridx[64], e2i[64], e3i[64];
    int t = threadIdx.x;                     // 256 threads
    if (t < 64)            ridx[t]       = r_idx[t];
    else if (t < 128)      e2i[t - 64]   = e2_idx[t - 64];
    else if (t < 192)      e3i[t - 128]  = e3_idx[t - 128];
    __syncthreads();

    for (int i = t; i < 2048; i += 256) {
        int b = i >> 5, d = i & 31;
        shr[i] = R[(size_t)ridx[b] * 32 + d];
        sh2[i] = E[(size_t)e2i[b] * 32 + d];
        sh3[i] = E[(size_t)e3i[b] * 32 + d];
    }
    if (t >= 224) {                          // last warp: p[r] = P.sum(-1)
        int r = t - 224;
        const float4* row = reinterpret_cast<const float4*>(P + r * 32);
        float s = 0.f;
        #pragma unroll
        for (int q = 0; q < 8; q++) { float4 v = row[q]; s += (v.x+v.y)+(v.z+v.w); }
        g_p[r] = s;
    }
    __syncthreads();

    int w = t >> 5, l = t & 31;
    if (w < 3) {                             // warp w does BN #w
        const float* sh  = (w == 0) ? shr : (w == 1) ? sh2 : sh3;
        const float* gg  = (w == 0) ? gr  : ge;
        const float* bb  = (w == 0) ? br  : be;
        float* dst       = (w == 0) ? g_remb : (w == 1) ? g_e2 : g_e3;
        float m = 0.f;
        #pragma unroll 8
        for (int b = 0; b < 64; b++) m += sh[b * 32 + l];
        m *= (1.f / 64.f);
        float v = 0.f;
        #pragma unroll 8
        for (int b = 0; b < 64; b++) { float d = sh[b * 32 + l] - m; v += d * d; }
        v *= (1.f / 64.f);
        float sc = gg[l] * rsqrtf(v + EPS);
        float of = bb[l] - m * sc;
        #pragma unroll 8
        for (int b = 0; b < 64; b++) dst[b * 32 + l] = sh[b * 32 + l] * sc + of;
    }
}

// ---------------- K3: per-batch contraction (64 blocks, 1 per b) -----------
__global__ void contract_kernel(const float* __restrict__ U_root,
                                const int* __restrict__ r_idx,
                                const int* __restrict__ miss_p)
{
    int b = blockIdx.x, t = threadIdx.x;
    int wid = t >> 5, lane = t & 31;
    int miss = miss_p ? *miss_p : 3;

    __shared__ float A1s[32], A2s[32], Vs[32];
    __shared__ float m[1024];                // outer product A1⊗A2
    __shared__ float y[1024];                // coef[r]*V[j]
    __shared__ float afr[32];                // a[b][r] = U_root[ridx[b]][r].sum()
    __shared__ float coef[32];
    __shared__ float partial[8][32];

    // gather + rowsum of U_root[ridx[b]] : thread t handles (r = t>>3, seg = t&7)
    {
        int ridx = r_idx[b];
        const float4* seg = reinterpret_cast<const float4*>(
            U_root + ((size_t)ridx * 32 + (t >> 3)) * 32) + (t & 7);
        float4 v = *seg;
        float s = (v.x + v.y) + (v.z + v.w);
        s += __shfl_down_sync(0xffffffffu, s, 4, 8);
        s += __shfl_down_sync(0xffffffffu, s, 2, 8);
        s += __shfl_down_sync(0xffffffffu, s, 1, 8);
        if ((t & 7) == 0) afr[t >> 3] = s;
    }

    if (t < 32) {
        if (miss == 1) { A1s[t] = g_e2[b*32+t];  A2s[t] = g_e3[b*32+t]; Vs[t] = g_remb[b*32+t]; }
        else           { A1s[t] = g_remb[b*32+t]; A2s[t] = g_e2[b*32+t]; Vs[t] = g_e3[b*32+t]; }
    }
    __syncthreads();
    for (int i = t; i < 1024; i += 256) m[i] = A1s[i >> 5] * A2s[i & 31];
    __syncthreads();

    const float* SU = (miss == 1) ? g_u3red  : g_u12red;   // scalar side
    const float* TU = (miss == 1) ? g_u12red : g_u3red;    // vector side

    // coef[r] = (Σ_ii SU[r,ii]*m[ii]) * a[b,r] * p[r]; warp wid owns r in [4w,4w+4)
    #pragma unroll
    for (int rr = 0; rr < 4; rr++) {
        int r = wid * 4 + rr;
        const float4* row = reinterpret_cast<const float4*>(SU + (size_t)r * 1024);
        float s = 0.f;
        #pragma unroll
        for (int q = 0; q < 8; q++) {
            float4 u = row[q * 32 + lane];
            const float4 mm = reinterpret_cast<const float4*>(m)[q * 32 + lane];
            s += u.x * mm.x + u.y * mm.y + u.z * mm.z + u.w * mm.w;
        }
        #pragma unroll
        for (int off = 16; off; off >>= 1)
            s += __shfl_down_sync(0xffffffffu, s, off);
        if (lane == 0) coef[r] = s * afr[r] * g_p[r];
    }
    __syncthreads();
    for (int i = t; i < 1024; i += 256) y[i] = coef[i >> 5] * Vs[i & 31];
    __syncthreads();

    // output: thread (k=t&31, part=t>>5); part owns r in [4p,4p+4)
    int k = t & 31, part = t >> 5;
    float acc = 0.f;
    if (miss == 2) {
        #pragma unroll
        for (int rr = 0; rr < 4; rr++) {
            int r = part * 4 + rr;
            const float4* seg = reinterpret_cast<const float4*>(TU + (size_t)r * 1024 + k * 32);
            #pragma unroll
            for (int q = 0; q < 8; q++) {
                float4 u = seg[q];
                acc += u.x * y[r*32 + q*4]   + u.y * y[r*32 + q*4+1]
                     + u.z * y[r*32 + q*4+2] + u.w * y[r*32 + q*4+3];
            }
        }
    } else {
        #pragma unroll
        for (int rr = 0; rr < 4; rr++) {
            int r = part * 4 + rr;
            #pragma unroll
            for (int j = 0; j < 32; j++)
                acc += y[r * 32 + j] * TU[(size_t)r * 1024 + j * 32 + k];
        }
    }
    partial[part][k] = acc;
    __syncthreads();
    if (t < 32) {
        float s = 0.f;
        #pragma unroll
        for (int p8 = 0; p8 < 8; p8++) s += partial[p8][t];
        g_vec[b * 32 + t] = s;
    }
}

// ---------------- K3b: BN(vec) -> g_vecn (256 threads, no spills) ----------
__global__ void bnvec_kernel(const float* __restrict__ gw, const float* __restrict__ bw)
{
    __shared__ float v[2048];
    __shared__ float sc_s[32], of_s[32];
    int t = threadIdx.x;                     // 256
    for (int i = t; i < 2048; i += 256) v[i] = g_vec[i];
    __syncthreads();
    if (t < 32) {
        float m = 0.f;
        #pragma unroll 8
        for (int b = 0; b < 64; b++) m += v[b * 32 + t];
        m *= (1.f / 64.f);
        float var = 0.f;
        #pragma unroll 8
        for (int b = 0; b < 64; b++) { float d = v[b * 32 + t] - m; var += d * d; }
        var *= (1.f / 64.f);
        float sc = gw[t] * rsqrtf(var + EPS);
        sc_s[t] = sc;
        of_s[t] = bw[t] - m * sc;
    }
    __syncthreads();
    for (int i = t; i < 2048; i += 256)
        g_vecn[i] = v[i] * sc_s[i & 31] + of_s[i & 31];
}

// ---------------- K4: logits + exp + per-block sums -------------------------
// Grid (391, 2), block 128. blockIdx.y selects a 32-row b-half; each thread
// owns ONE entity (er in 32 regs) and loops over 32 b's in chunks of 4.
__global__ void logits_kernel(const float* __restrict__ E, float* __restrict__ out)
{
    __shared__ float4 vecn4[256];            // this half's BN'd vec: [32 b][8 q]
    __shared__ float  wsum[32][4];
    int t = threadIdx.x;                     // 128
    int bhalf = blockIdx.y;                  // 0 or 1
    {
        const float4* src = reinterpret_cast<const float4*>(g_vecn) + bhalf * 256;
        for (int i = t; i < 256; i += 128) vecn4[i] = src[i];
    }
    __syncthreads();

    int n = blockIdx.x * 128 + t;
    bool valid = n < ENT;
    float4 er[8];
    if (valid) {
        const float4* p = reinterpret_cast<const float4*>(E + (size_t)n * 32);
        #pragma unroll
        for (int q = 0; q < 8; q++) er[q] = p[q];
    } else {
        #pragma unroll
        for (int q = 0; q < 8; q++) er[q] = make_float4(0.f, 0.f, 0.f, 0.f);
    }

    int wid = t >> 5, lane = t & 31;
    size_t outbase = (size_t)(bhalf * 32) * ENT + n;

    #pragma unroll
    for (int c = 0; c < 8; c++) {            // 8 chunks of 4 b's
        int bl = c * 4;
        float l0 = 0.f, l1 = 0.f, l2 = 0.f, l3 = 0.f;
        #pragma unroll
        for (int q = 0; q < 8; q++) {
            float4 e  = er[q];
            float4 w0 = vecn4[(bl + 0) * 8 + q];
            float4 w1 = vecn4[(bl + 1) * 8 + q];
            float4 w2 = vecn4[(bl + 2) * 8 + q];
            float4 w3 = vecn4[(bl + 3) * 8 + q];
            l0 += w0.x*e.x + w0.y*e.y + w0.z*e.z + w0.w*e.w;
            l1 += w1.x*e.x + w1.y*e.y + w1.z*e.z + w1.w*e.w;
            l2 += w2.x*e.x + w2.y*e.y + w2.z*e.z + w2.w*e.w;
            l3 += w3.x*e.x + w3.y*e.y + w3.z*e.z + w3.w*e.w;
        }
        float p0 = valid ? exp_small(l0) : 0.f;
        float p1 = valid ? exp_small(l1) : 0.f;
        float p2 = valid ? exp_small(l2) : 0.f;
        float p3 = valid ? exp_small(l3) : 0.f;
        if (valid) {
            out[outbase + (size_t)(bl + 0) * ENT] = p0;
            out[outbase + (size_t)(bl + 1) * ENT] = p1;
            out[outbase + (size_t)(bl + 2) * ENT] = p2;
            out[outbase + (size_t)(bl + 3) * ENT] = p3;
        }
        #pragma unroll
        for (int off = 16; off; off >>= 1) {
            p0 += __shfl_down_sync(0xffffffffu, p0, off);
            p1 += __shfl_down_sync(0xffffffffu, p1, off);
            p2 += __shfl_down_sync(0xffffffffu, p2, off);
            p3 += __shfl_down_sync(0xffffffffu, p3, off);
        }
        if (lane == 0) {
            wsum[bl + 0][wid] = p0; wsum[bl + 1][wid] = p1;
            wsum[bl + 2][wid] = p2; wsum[bl + 3][wid] = p3;
        }
    }
    __syncthreads();
    if (t < 32)
        g_bsum[blockIdx.x * 64 + bhalf * 32 + t] =
            (wsum[t][0] + wsum[t][1]) + (wsum[t][2] + wsum[t][3]);
}

// ---------------- K5: normalize (denominator reduced inline per block) -----
__global__ void norm_kernel(float* __restrict__ out, int nblk)
{
    __shared__ float red[256];
    int b = blockIdx.y, t = threadIdx.x;
    float s = 0.f;
    for (int q = t; q < nblk; q += 256) s += g_bsum[q * 64 + b];
    red[t] = s;
    __syncthreads();
    #pragma unroll
    for (int off = 128; off; off >>= 1) {
        if (t < off) red[t] += red[t + off];
        __syncthreads();
    }
    float inv = 1.f / red[0];

    int i = blockIdx.x * 256 + t;            // float4 index within row (12500 per row)
    if (i < 12500) {
        float4* p = reinterpret_cast<float4*>(out + (size_t)b * ENT);
        float4 v = p[i];
        v.x *= inv; v.y *= inv; v.z *= inv; v.w *= inv;
        p[i] = v;
    }
}

// ---------------- launch ----------------------------------------------------
extern "C" void kernel_launch(void* const* d_in, const int* in_sizes, int n_in,
                              void* d_out, int out_size)
{
    const float* E      = (const float*)d_in[0];
    const float* R      = (const float*)d_in[1];
    const float* U_root = (const float*)d_in[2];
    const float* U12    = (const float*)d_in[3];
    const float* U3R    = (const float*)d_in[4];
    const float* P      = (const float*)d_in[5];
    const float* gr     = (const float*)d_in[6];
    const float* br     = (const float*)d_in[7];
    const float* ge     = (const float*)d_in[8];
    const float* be     = (const float*)d_in[9];
    const float* gw     = (const float*)d_in[10];
    const float* bw     = (const float*)d_in[11];
    const int* r_idx    = (const int*)d_in[12];
    const int* e2_idx   = (const int*)d_in[13];
    const int* e3_idx   = (const int*)d_in[14];
    const int* miss     = (n_in > 15) ? (const int*)d_in[15] : nullptr;
    float* out = (float*)d_out;

    reduce_kernel<<<8192, 256>>>(U12, U3R);
    prep_kernel<<<1, 256>>>(E, R, P, gr, br, ge, be, r_idx, e2_idx, e3_idx);
    contract_kernel<<<64, 256>>>(U_root, r_idx, miss);
    bnvec_kernel<<<1, 256>>>(gw, bw);
    logits_kernel<<<dim3(LOG_BLKS, 2), 128>>>(E, out);
    norm_kernel<<<dim3((12500 + 255) / 256, 64), 256>>>(out, LOG_BLKS);
}

// round 9
// speedup vs baseline: 1.0828x; 1.0645x over previous
#include <cuda_runtime.h>
#include <cstdint>

#define EPS 1e-5f

// ---------------- scratch (device globals; allocation-free) ----------------
__device__ float g_u12red[32 * 1024];       // [r, ii]  sum over last axis of U12
__device__ float g_u3red [32 * 1024];       // [r, jj]  sum over last axis of U3R
__device__ float g_vec [64 * 32];           // vec (pre-BN)
__device__ float g_bsum[512 * 64];          // per-logit-block exp partial sums

static const int ENT = 50000;
static const int LOG_BLKS = (ENT + 127) / 128;   // 391 (128 entities per block)

// exp(x) for small |x| via degree-6 Taylor (pure FFMA, no MUFU).
// Logits here are |x| <~ 0.04 by construction; fallback for safety.
__device__ __forceinline__ float exp_small(float x)
{
    if (fabsf(x) > 0.6f) return __expf(x);   // never taken in practice
    float p = 1.388888889e-3f;               // 1/720
    p = fmaf(p, x, 8.333333333e-3f);         // 1/120
    p = fmaf(p, x, 4.166666667e-2f);         // 1/24
    p = fmaf(p, x, 1.666666667e-1f);         // 1/6
    p = fmaf(p, x, 0.5f);
    p = fmaf(p, x, 1.0f);
    p = fmaf(p, x, 1.0f);
    return p;
}

// ---------------- K1: row reduction of U12 and U3R (the 256 MB stream) -----
__global__ void reduce_kernel(const float* __restrict__ U12,
                              const float* __restrict__ U3R)
{
    int gw   = (blockIdx.x * 256 + threadIdx.x) >> 5;   // global warp id, 65536 total
    int lane = threadIdx.x & 31;
    const float* src;
    float* dst;
    int row;
    if (gw < 32768) { src = U12; dst = g_u12red; row = gw; }
    else            { src = U3R; dst = g_u3red;  row = gw - 32768; }

    const float4* p = reinterpret_cast<const float4*>(src + (size_t)row * 1024) + lane;
    float4 a0 = p[0],   a1 = p[32],  a2 = p[64],  a3 = p[96];
    float4 a4 = p[128], a5 = p[160], a6 = p[192], a7 = p[224];
    float s = ((a0.x + a0.y) + (a0.z + a0.w)) + ((a1.x + a1.y) + (a1.z + a1.w))
            + ((a2.x + a2.y) + (a2.z + a2.w)) + ((a3.x + a3.y) + (a3.z + a3.w))
            + ((a4.x + a4.y) + (a4.z + a4.w)) + ((a5.x + a5.y) + (a5.z + a5.w))
            + ((a6.x + a6.y) + (a6.z + a6.w)) + ((a7.x + a7.y) + (a7.z + a7.w));
    #pragma unroll
    for (int off = 16; off; off >>= 1)
        s += __shfl_down_sync(0xffffffffu, s, off);
    if (lane == 0) dst[row] = s;
}

// ---------------- K2: fused prep + per-batch contraction (64 blocks) -------
// Each block b redundantly computes the BN statistics (over all 64 rows,
// gathered fresh - L2-hot, deterministic) and normalizes only its own row.
__global__ void contract_kernel(const float* __restrict__ E,
                                const float* __restrict__ R,
                                const float* __restrict__ U_root,
                                const float* __restrict__ P,
                                const float* __restrict__ gr, const float* __restrict__ br,
                                const float* __restrict__ ge, const float* __restrict__ be,
                                const int* __restrict__ r_idx,
                                const int* __restrict__ e2_idx,
                                const int* __restrict__ e3_idx,
                                const int* __restrict__ miss_p)
{
    int b = blockIdx.x, t = threadIdx.x;     // 256 threads
    int wid = t >> 5, lane = t & 31;
    int miss = miss_p ? *miss_p : 3;

    __shared__ float shr[2048], sh2[2048], sh3[2048];
    __shared__ int   idxs[192];              // [0:64) r, [64:128) e2, [128:192) e3
    __shared__ float Rn[32], E2n[32], E3n[32];
    __shared__ float A1s[32], A2s[32], Vs[32];
    __shared__ float m[1024];                // outer product A1⊗A2
    __shared__ float y[1024];                // coef[r]*V[j]
    __shared__ float afr[32];                // a[b][r] = U_root[ridx[b]][r].sum()
    __shared__ float p_sh[32];               // p[r] = P[r].sum()
    __shared__ float coef[32];
    __shared__ float partial[8][32];

    if (t < 64)        idxs[t]       = r_idx[t];
    else if (t < 128)  idxs[t]       = e2_idx[t - 64];
    else if (t < 192)  idxs[t]       = e3_idx[t - 128];
    __syncthreads();

    // gather all 64 rows of each (for BN stats)
    for (int i = t; i < 2048; i += 256) {
        int bb = i >> 5, d = i & 31;
        shr[i] = R[(size_t)idxs[bb] * 32 + d];
        sh2[i] = E[(size_t)idxs[64 + bb] * 32 + d];
        sh3[i] = E[(size_t)idxs[128 + bb] * 32 + d];
    }
    // warp 7: p[r] = P.sum(-1)
    if (wid == 7) {
        const float4* row = reinterpret_cast<const float4*>(P + lane * 32);
        float s = 0.f;
        #pragma unroll
        for (int q = 0; q < 8; q++) { float4 v = row[q]; s += (v.x+v.y)+(v.z+v.w); }
        p_sh[lane] = s;
    }
    // all threads: afr[r] = U_root[ridx[b]][r].sum(); thread (r=t>>3, seg=t&7)
    {
        int ridx = r_idx[b];
        const float4* seg = reinterpret_cast<const float4*>(
            U_root + ((size_t)ridx * 32 + (t >> 3)) * 32) + (t & 7);
        float4 v = *seg;
        float s = (v.x + v.y) + (v.z + v.w);
        s += __shfl_down_sync(0xffffffffu, s, 4, 8);
        s += __shfl_down_sync(0xffffffffu, s, 2, 8);
        s += __shfl_down_sync(0xffffffffu, s, 1, 8);
        if ((t & 7) == 0) afr[t >> 3] = s;
    }
    __syncthreads();

    // warps 0..2: BN stats for R / e2 / e3, normalize ONLY row b
    if (wid < 3) {
        const float* sh  = (wid == 0) ? shr : (wid == 1) ? sh2 : sh3;
        const float* gg  = (wid == 0) ? gr  : ge;
        const float* bb  = (wid == 0) ? br  : be;
        float* dst       = (wid == 0) ? Rn  : (wid == 1) ? E2n : E3n;
        float mm = 0.f;
        #pragma unroll 8
        for (int q = 0; q < 64; q++) mm += sh[q * 32 + lane];
        mm *= (1.f / 64.f);
        float var = 0.f;
        #pragma unroll 8
        for (int q = 0; q < 64; q++) { float d = sh[q * 32 + lane] - mm; var += d * d; }
        var *= (1.f / 64.f);
        float sc = gg[lane] * rsqrtf(var + EPS);
        float of = bb[lane] - mm * sc;
        dst[lane] = sh[b * 32 + lane] * sc + of;
    }
    __syncthreads();

    if (t < 32) {
        if (miss == 1) { A1s[t] = E2n[t]; A2s[t] = E3n[t]; Vs[t] = Rn[t]; }
        else           { A1s[t] = Rn[t];  A2s[t] = E2n[t]; Vs[t] = E3n[t]; }
    }
    __syncthreads();
    for (int i = t; i < 1024; i += 256) m[i] = A1s[i >> 5] * A2s[i & 31];
    __syncthreads();

    const float* SU = (miss == 1) ? g_u3red  : g_u12red;   // scalar side
    const float* TU = (miss == 1) ? g_u12red : g_u3red;    // vector side

    // coef[r] = (Σ_ii SU[r,ii]*m[ii]) * afr[r] * p[r]; warp wid owns r in [4w,4w+4)
    #pragma unroll
    for (int rr = 0; rr < 4; rr++) {
        int r = wid * 4 + rr;
        const float4* row = reinterpret_cast<const float4*>(SU + (size_t)r * 1024);
        float s = 0.f;
        #pragma unroll
        for (int q = 0; q < 8; q++) {
            float4 u = row[q * 32 + lane];
            const float4 mm = reinterpret_cast<const float4*>(m)[q * 32 + lane];
            s += u.x * mm.x + u.y * mm.y + u.z * mm.z + u.w * mm.w;
        }
        #pragma unroll
        for (int off = 16; off; off >>= 1)
            s += __shfl_down_sync(0xffffffffu, s, off);
        if (lane == 0) coef[r] = s * afr[r] * p_sh[r];
    }
    __syncthreads();
    for (int i = t; i < 1024; i += 256) y[i] = coef[i >> 5] * Vs[i & 31];
    __syncthreads();

    // output: thread (k=t&31, part=t>>5); part owns r in [4p,4p+4)
    int k = t & 31, part = t >> 5;
    float acc = 0.f;
    if (miss == 2) {
        #pragma unroll
        for (int rr = 0; rr < 4; rr++) {
            int r = part * 4 + rr;
            const float4* seg = reinterpret_cast<const float4*>(TU + (size_t)r * 1024 + k * 32);
            #pragma unroll
            for (int q = 0; q < 8; q++) {
                float4 u = seg[q];
                acc += u.x * y[r*32 + q*4]   + u.y * y[r*32 + q*4+1]
                     + u.z * y[r*32 + q*4+2] + u.w * y[r*32 + q*4+3];
            }
        }
    } else {
        #pragma unroll
        for (int rr = 0; rr < 4; rr++) {
            int r = part * 4 + rr;
            #pragma unroll
            for (int j = 0; j < 32; j++)
                acc += y[r * 32 + j] * TU[(size_t)r * 1024 + j * 32 + k];
        }
    }
    partial[part][k] = acc;
    __syncthreads();
    if (t < 32) {
        float s = 0.f;
        #pragma unroll
        for (int p8 = 0; p8 < 8; p8++) s += partial[p8][t];
        g_vec[b * 32 + t] = s;
    }
}

// ---------------- K3: logits + exp + per-block sums (BN(vec) inline) -------
// Grid (391, 2), block 128. blockIdx.y selects a 32-row b-half; each thread
// owns ONE entity (er in 32 regs) and loops over 32 b's in chunks of 4.
__global__ void logits_kernel(const float* __restrict__ E,
                              const float* __restrict__ gw,
                              const float* __restrict__ bw,
                              float* __restrict__ out)
{
    __shared__ float  vraw[2048];
    __shared__ float  sc_s[32], of_s[32];
    __shared__ float4 vecn4[256];            // this half's BN'd vec: [32 b][8 q]
    __shared__ float  wsum[32][4];
    int t = threadIdx.x;                     // 128
    int bhalf = blockIdx.y;                  // 0 or 1
    for (int i = t; i < 2048; i += 128) vraw[i] = g_vec[i];
    __syncthreads();
    if (t < 32) {                            // BN stats over all 64 b (redundant per block)
        float m = 0.f;
        #pragma unroll 8
        for (int q = 0; q < 64; q++) m += vraw[q * 32 + t];
        m *= (1.f / 64.f);
        float var = 0.f;
        #pragma unroll 8
        for (int q = 0; q < 64; q++) { float d = vraw[q * 32 + t] - m; var += d * d; }
        var *= (1.f / 64.f);
        float sc = gw[t] * rsqrtf(var + EPS);
        sc_s[t] = sc;
        of_s[t] = bw[t] - m * sc;
    }
    __syncthreads();
    {
        float* vecnf = reinterpret_cast<float*>(vecn4);
        for (int i = t; i < 1024; i += 128) {
            int src = bhalf * 1024 + i;
            vecnf[i] = vraw[src] * sc_s[i & 31] + of_s[i & 31];
        }
    }
    __syncthreads();

    int n = blockIdx.x * 128 + t;
    bool valid = n < ENT;
    float4 er[8];
    if (valid) {
        const float4* p = reinterpret_cast<const float4*>(E + (size_t)n * 32);
        #pragma unroll
        for (int q = 0; q < 8; q++) er[q] = p[q];
    } else {
        #pragma unroll
        for (int q = 0; q < 8; q++) er[q] = make_float4(0.f, 0.f, 0.f, 0.f);
    }

    int wid = t >> 5, lane = t & 31;
    size_t outbase = (size_t)(bhalf * 32) * ENT + n;

    #pragma unroll
    for (int c = 0; c < 8; c++) {            // 8 chunks of 4 b's
        int bl = c * 4;
        float l0 = 0.f, l1 = 0.f, l2 = 0.f, l3 = 0.f;
        #pragma unroll
        for (int q = 0; q < 8; q++) {
            float4 e  = er[q];
            float4 w0 = vecn4[(bl + 0) * 8 + q];
            float4 w1 = vecn4[(bl + 1) * 8 + q];
            float4 w2 = vecn4[(bl + 2) * 8 + q];
            float4 w3 = vecn4[(bl + 3) * 8 + q];
            l0 += w0.x*e.x + w0.y*e.y + w0.z*e.z + w0.w*e.w;
            l1 += w1.x*e.x + w1.y*e.y + w1.z*e.z + w1.w*e.w;
            l2 += w2.x*e.x + w2.y*e.y + w2.z*e.z + w2.w*e.w;
            l3 += w3.x*e.x + w3.y*e.y + w3.z*e.z + w3.w*e.w;
        }
        float p0 = valid ? exp_small(l0) : 0.f;
        float p1 = valid ? exp_small(l1) : 0.f;
        float p2 = valid ? exp_small(l2) : 0.f;
        float p3 = valid ? exp_small(l3) : 0.f;
        if (valid) {
            out[outbase + (size_t)(bl + 0) * ENT] = p0;
            out[outbase + (size_t)(bl + 1) * ENT] = p1;
            out[outbase + (size_t)(bl + 2) * ENT] = p2;
            out[outbase + (size_t)(bl + 3) * ENT] = p3;
        }
        #pragma unroll
        for (int off = 16; off; off >>= 1) {
            p0 += __shfl_down_sync(0xffffffffu, p0, off);
            p1 += __shfl_down_sync(0xffffffffu, p1, off);
            p2 += __shfl_down_sync(0xffffffffu, p2, off);
            p3 += __shfl_down_sync(0xffffffffu, p3, off);
        }
        if (lane == 0) {
            wsum[bl + 0][wid] = p0; wsum[bl + 1][wid] = p1;
            wsum[bl + 2][wid] = p2; wsum[bl + 3][wid] = p3;
        }
    }
    __syncthreads();
    if (t < 32)
        g_bsum[blockIdx.x * 64 + bhalf * 32 + t] =
            (wsum[t][0] + wsum[t][1]) + (wsum[t][2] + wsum[t][3]);
}

// ---------------- K4: normalize (denominator reduced inline per block) -----
__global__ void norm_kernel(float* __restrict__ out, int nblk)
{
    __shared__ float red[256];
    int b = blockIdx.y, t = threadIdx.x;
    float s = 0.f;
    for (int q = t; q < nblk; q += 256) s += g_bsum[q * 64 + b];
    red[t] = s;
    __syncthreads();
    #pragma unroll
    for (int off = 128; off; off >>= 1) {
        if (t < off) red[t] += red[t + off];
        __syncthreads();
    }
    float inv = 1.f / red[0];

    int i = blockIdx.x * 256 + t;            // float4 index within row (12500 per row)
    if (i < 12500) {
        float4* p = reinterpret_cast<float4*>(out + (size_t)b * ENT);
        float4 v = p[i];
        v.x *= inv; v.y *= inv; v.z *= inv; v.w *= inv;
        p[i] = v;
    }
}

// ---------------- launch ----------------------------------------------------
extern "C" void kernel_launch(void* const* d_in, const int* in_sizes, int n_in,
                              void* d_out, int out_size)
{
    const float* E      = (const float*)d_in[0];
    const float* R      = (const float*)d_in[1];
    const float* U_root = (const float*)d_in[2];
    const float* U12    = (const float*)d_in[3];
    const float* U3R    = (const float*)d_in[4];
    const float* P      = (const float*)d_in[5];
    const float* gr     = (const float*)d_in[6];
    const float* br     = (const float*)d_in[7];
    const float* ge     = (const float*)d_in[8];
    const float* be     = (const float*)d_in[9];
    const float* gw     = (const float*)d_in[10];
    const float* bw     = (const float*)d_in[11];
    const int* r_idx    = (const int*)d_in[12];
    const int* e2_idx   = (const int*)d_in[13];
    const int* e3_idx   = (const int*)d_in[14];
    const int* miss     = (n_in > 15) ? (const int*)d_in[15] : nullptr;
    float* out = (float*)d_out;

    reduce_kernel<<<8192, 256>>>(U12, U3R);
    contract_kernel<<<64, 256>>>(E, R, U_root, P, gr, br, ge, be,
                                 r_idx, e2_idx, e3_idx, miss);
    logits_kernel<<<dim3(LOG_BLKS, 2), 128>>>(E, gw, bw, out);
    norm_kernel<<<dim3((12500 + 255) / 256, 64), 256>>>(out, LOG_BLKS);
}

// round 11
// speedup vs baseline: 1.1525x; 1.0644x over previous
#include <cuda_runtime.h>
#include <cstdint>

#define EPS 1e-5f

// ---------------- scratch (device globals; allocation-free) ----------------
__device__ float g_u12red[32 * 1024];       // [r, ii]  sum over last axis of U12
__device__ float g_u3red [32 * 1024];       // [r, jj]  sum over last axis of U3R
__device__ float g_vec [64 * 32];           // vec (pre-BN)
__device__ float g_bsum[64 * 512];          // per-b, per-logit-block exp partials (TRANSPOSED)

static const int ENT = 50000;
static const int LOG_BLKS = (ENT + 127) / 128;   // 391 (128 entities per block)

// exp(x) for small |x| via degree-6 Taylor (pure FFMA, no MUFU).
// Logits here are |x| <~ 0.04 by construction; fallback for safety.
__device__ __forceinline__ float exp_small(float x)
{
    if (fabsf(x) > 0.6f) return __expf(x);   // never taken in practice
    float p = 1.388888889e-3f;               // 1/720
    p = fmaf(p, x, 8.333333333e-3f);         // 1/120
    p = fmaf(p, x, 4.166666667e-2f);         // 1/24
    p = fmaf(p, x, 1.666666667e-1f);         // 1/6
    p = fmaf(p, x, 0.5f);
    p = fmaf(p, x, 1.0f);
    p = fmaf(p, x, 1.0f);
    return p;
}

// ---------------- K1: row reduction of U12 and U3R (the 256 MB stream) -----
__global__ void reduce_kernel(const float* __restrict__ U12,
                              const float* __restrict__ U3R)
{
    int gw   = (blockIdx.x * 256 + threadIdx.x) >> 5;   // global warp id, 65536 total
    int lane = threadIdx.x & 31;
    const float* src;
    float* dst;
    int row;
    if (gw < 32768) { src = U12; dst = g_u12red; row = gw; }
    else            { src = U3R; dst = g_u3red;  row = gw - 32768; }

    const float4* p = reinterpret_cast<const float4*>(src + (size_t)row * 1024) + lane;
    float4 a0 = p[0],   a1 = p[32],  a2 = p[64],  a3 = p[96];
    float4 a4 = p[128], a5 = p[160], a6 = p[192], a7 = p[224];
    float s = ((a0.x + a0.y) + (a0.z + a0.w)) + ((a1.x + a1.y) + (a1.z + a1.w))
            + ((a2.x + a2.y) + (a2.z + a2.w)) + ((a3.x + a3.y) + (a3.z + a3.w))
            + ((a4.x + a4.y) + (a4.z + a4.w)) + ((a5.x + a5.y) + (a5.z + a5.w))
            + ((a6.x + a6.y) + (a6.z + a6.w)) + ((a7.x + a7.y) + (a7.z + a7.w));
    #pragma unroll
    for (int off = 16; off; off >>= 1)
        s += __shfl_down_sync(0xffffffffu, s, off);
    if (lane == 0) dst[row] = s;
}

// ---------------- K2: fused prep + per-batch contraction (64 blocks) -------
__global__ void contract_kernel(const float* __restrict__ E,
                                const float* __restrict__ R,
                                const float* __restrict__ U_root,
                                const float* __restrict__ P,
                                const float* __restrict__ gr, const float* __restrict__ br,
                                const float* __restrict__ ge, const float* __restrict__ be,
                                const int* __restrict__ r_idx,
                                const int* __restrict__ e2_idx,
                                const int* __restrict__ e3_idx,
                                const int* __restrict__ miss_p)
{
    int b = blockIdx.x, t = threadIdx.x;     // 256 threads
    int wid = t >> 5, lane = t & 31;
    int miss = miss_p ? *miss_p : 3;

    __shared__ float shr[2048], sh2[2048], sh3[2048];
    __shared__ int   idxs[192];              // [0:64) r, [64:128) e2, [128:192) e3
    __shared__ float Rn[32], E2n[32], E3n[32];
    __shared__ float A1s[32], A2s[32], Vs[32];
    __shared__ float m[1024];                // outer product A1⊗A2
    __shared__ float y[1024];                // coef[r]*V[j]
    __shared__ float afr[32];                // a[b][r] = U_root[ridx[b]][r].sum()
    __shared__ float p_sh[32];               // p[r] = P[r].sum()
    __shared__ float coef[32];
    __shared__ float partial[8][32];

    if (t < 64)        idxs[t]       = r_idx[t];
    else if (t < 128)  idxs[t]       = e2_idx[t - 64];
    else if (t < 192)  idxs[t]       = e3_idx[t - 128];
    __syncthreads();

    // gather all 64 rows of each (for BN stats)
    for (int i = t; i < 2048; i += 256) {
        int bb = i >> 5, d = i & 31;
        shr[i] = R[(size_t)idxs[bb] * 32 + d];
        sh2[i] = E[(size_t)idxs[64 + bb] * 32 + d];
        sh3[i] = E[(size_t)idxs[128 + bb] * 32 + d];
    }
    // warp 7: p[r] = P.sum(-1)
    if (wid == 7) {
        const float4* row = reinterpret_cast<const float4*>(P + lane * 32);
        float s = 0.f;
        #pragma unroll
        for (int q = 0; q < 8; q++) { float4 v = row[q]; s += (v.x+v.y)+(v.z+v.w); }
        p_sh[lane] = s;
    }
    // all threads: afr[r] = U_root[ridx[b]][r].sum(); thread (r=t>>3, seg=t&7)
    {
        int ridx = r_idx[b];
        const float4* seg = reinterpret_cast<const float4*>(
            U_root + ((size_t)ridx * 32 + (t >> 3)) * 32) + (t & 7);
        float4 v = *seg;
        float s = (v.x + v.y) + (v.z + v.w);
        s += __shfl_down_sync(0xffffffffu, s, 4, 8);
        s += __shfl_down_sync(0xffffffffu, s, 2, 8);
        s += __shfl_down_sync(0xffffffffu, s, 1, 8);
        if ((t & 7) == 0) afr[t >> 3] = s;
    }
    __syncthreads();

    // warps 0..2: BN stats for R / e2 / e3, normalize ONLY row b
    if (wid < 3) {
        const float* sh  = (wid == 0) ? shr : (wid == 1) ? sh2 : sh3;
        const float* gg  = (wid == 0) ? gr  : ge;
        const float* bb  = (wid == 0) ? br  : be;
        float* dst       = (wid == 0) ? Rn  : (wid == 1) ? E2n : E3n;
        float mm = 0.f;
        #pragma unroll 8
        for (int q = 0; q < 64; q++) mm += sh[q * 32 + lane];
        mm *= (1.f / 64.f);
        float var = 0.f;
        #pragma unroll 8
        for (int q = 0; q < 64; q++) { float d = sh[q * 32 + lane] - mm; var += d * d; }
        var *= (1.f / 64.f);
        float sc = gg[lane] * rsqrtf(var + EPS);
        float of = bb[lane] - mm * sc;
        dst[lane] = sh[b * 32 + lane] * sc + of;
    }
    __syncthreads();

    if (t < 32) {
        if (miss == 1) { A1s[t] = E2n[t]; A2s[t] = E3n[t]; Vs[t] = Rn[t]; }
        else           { A1s[t] = Rn[t];  A2s[t] = E2n[t]; Vs[t] = E3n[t]; }
    }
    __syncthreads();
    for (int i = t; i < 1024; i += 256) m[i] = A1s[i >> 5] * A2s[i & 31];
    __syncthreads();

    const float* SU = (miss == 1) ? g_u3red  : g_u12red;   // scalar side
    const float* TU = (miss == 1) ? g_u12red : g_u3red;    // vector side

    // coef[r] = (Σ_ii SU[r,ii]*m[ii]) * afr[r] * p[r]; warp wid owns r in [4w,4w+4)
    #pragma unroll
    for (int rr = 0; rr < 4; rr++) {
        int r = wid * 4 + rr;
        const float4* row = reinterpret_cast<const float4*>(SU + (size_t)r * 1024);
        float s = 0.f;
        #pragma unroll
        for (int q = 0; q < 8; q++) {
            float4 u = row[q * 32 + lane];
            const float4 mm = reinterpret_cast<const float4*>(m)[q * 32 + lane];
            s += u.x * mm.x + u.y * mm.y + u.z * mm.z + u.w * mm.w;
        }
        #pragma unroll
        for (int off = 16; off; off >>= 1)
            s += __shfl_down_sync(0xffffffffu, s, off);
        if (lane == 0) coef[r] = s * afr[r] * p_sh[r];
    }
    __syncthreads();
    for (int i = t; i < 1024; i += 256) y[i] = coef[i >> 5] * Vs[i & 31];
    __syncthreads();

    // output: thread (k=t&31, part=t>>5); part owns r in [4p,4p+4)
    int k = t & 31, part = t >> 5;
    float acc = 0.f;
    if (miss == 2) {
        #pragma unroll
        for (int rr = 0; rr < 4; rr++) {
            int r = part * 4 + rr;
            const float4* seg = reinterpret_cast<const float4*>(TU + (size_t)r * 1024 + k * 32);
            #pragma unroll
            for (int q = 0; q < 8; q++) {
                float4 u = seg[q];
                acc += u.x * y[r*32 + q*4]   + u.y * y[r*32 + q*4+1]
                     + u.z * y[r*32 + q*4+2] + u.w * y[r*32 + q*4+3];
            }
        }
    } else {
        #pragma unroll
        for (int rr = 0; rr < 4; rr++) {
            int r = part * 4 + rr;
            #pragma unroll
            for (int j = 0; j < 32; j++)
                acc += y[r * 32 + j] * TU[(size_t)r * 1024 + j * 32 + k];
        }
    }
    partial[part][k] = acc;
    __syncthreads();
    if (t < 32) {
        float s = 0.f;
        #pragma unroll
        for (int p8 = 0; p8 < 8; p8++) s += partial[p8][t];
        g_vec[b * 32 + t] = s;
    }
}

// ---------------- K3: logits + exp + per-block sums (BN(vec) inline) -------
// Grid (391, 2), block 128. blockIdx.y selects a 32-row b-half; each thread
// owns ONE entity (er in 32 regs) and loops over 32 b's in chunks of 4.
__global__ void logits_kernel(const float* __restrict__ E,
                              const float* __restrict__ gw,
                              const float* __restrict__ bw,
                              float* __restrict__ out)
{
    __shared__ float  vraw[2048];
    __shared__ float  sc_s[32], of_s[32];
    __shared__ float4 vecn4[256];            // this half's BN'd vec: [32 b][8 q]
    __shared__ float  wsum[32][4];
    int t = threadIdx.x;                     // 128
    int bhalf = blockIdx.y;                  // 0 or 1
    for (int i = t; i < 2048; i += 128) vraw[i] = g_vec[i];
    __syncthreads();
    if (t < 32) {                            // BN stats over all 64 b (redundant per block)
        float m = 0.f;
        #pragma unroll 8
        for (int q = 0; q < 64; q++) m += vraw[q * 32 + t];
        m *= (1.f / 64.f);
        float var = 0.f;
        #pragma unroll 8
        for (int q = 0; q < 64; q++) { float d = vraw[q * 32 + t] - m; var += d * d; }
        var *= (1.f / 64.f);
        float sc = gw[t] * rsqrtf(var + EPS);
        sc_s[t] = sc;
        of_s[t] = bw[t] - m * sc;
    }
    __syncthreads();
    {
        float* vecnf = reinterpret_cast<float*>(vecn4);
        for (int i = t; i < 1024; i += 128) {
            int src = bhalf * 1024 + i;
            vecnf[i] = vraw[src] * sc_s[i & 31] + of_s[i & 31];
        }
    }
    __syncthreads();

    int n = blockIdx.x * 128 + t;
    bool valid = n < ENT;
    float4 er[8];
    if (valid) {
        const float4* p = reinterpret_cast<const float4*>(E + (size_t)n * 32);
        #pragma unroll
        for (int q = 0; q < 8; q++) er[q] = p[q];
    } else {
        #pragma unroll
        for (int q = 0; q < 8; q++) er[q] = make_float4(0.f, 0.f, 0.f, 0.f);
    }

    int wid = t >> 5, lane = t & 31;
    size_t outbase = (size_t)(bhalf * 32) * ENT + n;

    #pragma unroll
    for (int c = 0; c < 8; c++) {            // 8 chunks of 4 b's
        int bl = c * 4;
        float l0 = 0.f, l1 = 0.f, l2 = 0.f, l3 = 0.f;
        #pragma unroll
        for (int q = 0; q < 8; q++) {
            float4 e  = er[q];
            float4 w0 = vecn4[(bl + 0) * 8 + q];
            float4 w1 = vecn4[(bl + 1) * 8 + q];
            float4 w2 = vecn4[(bl + 2) * 8 + q];
            float4 w3 = vecn4[(bl + 3) * 8 + q];
            l0 += w0.x*e.x + w0.y*e.y + w0.z*e.z + w0.w*e.w;
            l1 += w1.x*e.x + w1.y*e.y + w1.z*e.z + w1.w*e.w;
            l2 += w2.x*e.x + w2.y*e.y + w2.z*e.z + w2.w*e.w;
            l3 += w3.x*e.x + w3.y*e.y + w3.z*e.z + w3.w*e.w;
        }
        float p0 = valid ? exp_small(l0) : 0.f;
        float p1 = valid ? exp_small(l1) : 0.f;
        float p2 = valid ? exp_small(l2) : 0.f;
        float p3 = valid ? exp_small(l3) : 0.f;
        if (valid) {
            out[outbase + (size_t)(bl + 0) * ENT] = p0;
            out[outbase + (size_t)(bl + 1) * ENT] = p1;
            out[outbase + (size_t)(bl + 2) * ENT] = p2;
            out[outbase + (size_t)(bl + 3) * ENT] = p3;
        }
        #pragma unroll
        for (int off = 16; off; off >>= 1) {
            p0 += __shfl_down_sync(0xffffffffu, p0, off);
            p1 += __shfl_down_sync(0xffffffffu, p1, off);
            p2 += __shfl_down_sync(0xffffffffu, p2, off);
            p3 += __shfl_down_sync(0xffffffffu, p3, off);
        }
        if (lane == 0) {
            wsum[bl + 0][wid] = p0; wsum[bl + 1][wid] = p1;
            wsum[bl + 2][wid] = p2; wsum[bl + 3][wid] = p3;
        }
    }
    __syncthreads();
    if (t < 32)                              // transposed: [b][blk], coalesced for norm
        g_bsum[(size_t)(bhalf * 32 + t) * 512 + blockIdx.x] =
            (wsum[t][0] + wsum[t][1]) + (wsum[t][2] + wsum[t][3]);
}

// ---------------- K4: normalize ---------------------------------------------
// Grid (13, 64), 256 threads, 4 float4 per thread. Denominator reduce is
// coalesced (g_bsum transposed) and amortized over 4x payload.
__global__ void norm_kernel(float* __restrict__ out, int nblk)
{
    __shared__ float red[256];
    int b = blockIdx.y, t = threadIdx.x;
    float s = 0.f;
    for (int q = t; q < nblk; q += 256) s += g_bsum[(size_t)b * 512 + q];
    red[t] = s;
    __syncthreads();
    #pragma unroll
    for (int off = 128; off; off >>= 1) {
        if (t < off) red[t] += red[t + off];
        __syncthreads();
    }
    float inv = 1.f / red[0];

    float4* p = reinterpret_cast<float4*>(out + (size_t)b * ENT);
    int base = blockIdx.x * 1024 + t;        // float4 index (12500 per row)
    #pragma unroll
    for (int u = 0; u < 4; u++) {
        int i = base + u * 256;
        if (i < 12500) {
            float4 v = p[i];
            v.x *= inv; v.y *= inv; v.z *= inv; v.w *= inv;
            p[i] = v;
        }
    }
}

// ---------------- launch ----------------------------------------------------
extern "C" void kernel_launch(void* const* d_in, const int* in_sizes, int n_in,
                              void* d_out, int out_size)
{
    const float* E      = (const float*)d_in[0];
    const float* R      = (const float*)d_in[1];
    const float* U_root = (const float*)d_in[2];
    const float* U12    = (const float*)d_in[3];
    const float* U3R    = (const float*)d_in[4];
    const float* P      = (const float*)d_in[5];
    const float* gr     = (const float*)d_in[6];
    const float* br     = (const float*)d_in[7];
    const float* ge     = (const float*)d_in[8];
    const float* be     = (const float*)d_in[9];
    const float* gw     = (const float*)d_in[10];
    const float* bw     = (const float*)d_in[11];
    const int* r_idx    = (const int*)d_in[12];
    const int* e2_idx   = (const int*)d_in[13];
    const int* e3_idx   = (const int*)d_in[14];
    const int* miss     = (n_in > 15) ? (const int*)d_in[15] : nullptr;
    float* out = (float*)d_out;

    reduce_kernel<<<8192, 256>>>(U12, U3R);
    contract_kernel<<<64, 256>>>(E, R, U_root, P, gr, br, ge, be,
                                 r_idx, e2_idx, e3_idx, miss);
    logits_kernel<<<dim3(LOG_BLKS, 2), 128>>>(E, gw, bw, out);
    norm_kernel<<<dim3(13, 64), 256>>>(out, LOG_BLKS);
}

// round 12
// speedup vs baseline: 1.1617x; 1.0080x over previous
#include <cuda_runtime.h>
#include <cstdint>

#define EPS 1e-5f

// ---------------- scratch (device globals; allocation-free) ----------------
__device__ float g_u12red[32 * 1024];       // [r, ii]  sum over last axis of U12
__device__ float g_u3red [32 * 1024];       // [r, jj]  sum over last axis of U3R
__device__ float g_vec [64 * 32];           // vec (pre-BN)
__device__ float g_bsum[64 * 512];          // per-b, per-logit-block exp partials (TRANSPOSED)

static const int ENT = 50000;
static const int LOG_BLKS = (ENT + 127) / 128;   // 391 (128 entities per block)

// exp(x) for small |x| via degree-6 Taylor (pure FFMA, no MUFU).
// Logits here are |x| <~ 0.04 by construction; fallback for safety.
__device__ __forceinline__ float exp_small(float x)
{
    if (fabsf(x) > 0.6f) return __expf(x);   // never taken in practice
    float p = 1.388888889e-3f;               // 1/720
    p = fmaf(p, x, 8.333333333e-3f);         // 1/120
    p = fmaf(p, x, 4.166666667e-2f);         // 1/24
    p = fmaf(p, x, 1.666666667e-1f);         // 1/6
    p = fmaf(p, x, 0.5f);
    p = fmaf(p, x, 1.0f);
    p = fmaf(p, x, 1.0f);
    return p;
}

// ---------------- K1: row reduction of U12 and U3R (the 256 MB stream) -----
__global__ void reduce_kernel(const float* __restrict__ U12,
                              const float* __restrict__ U3R)
{
    int gw   = (blockIdx.x * 256 + threadIdx.x) >> 5;   // global warp id, 65536 total
    int lane = threadIdx.x & 31;
    const float* src;
    float* dst;
    int row;
    if (gw < 32768) { src = U12; dst = g_u12red; row = gw; }
    else            { src = U3R; dst = g_u3red;  row = gw - 32768; }

    const float4* p = reinterpret_cast<const float4*>(src + (size_t)row * 1024) + lane;
    float4 a0 = p[0],   a1 = p[32],  a2 = p[64],  a3 = p[96];
    float4 a4 = p[128], a5 = p[160], a6 = p[192], a7 = p[224];
    float s = ((a0.x + a0.y) + (a0.z + a0.w)) + ((a1.x + a1.y) + (a1.z + a1.w))
            + ((a2.x + a2.y) + (a2.z + a2.w)) + ((a3.x + a3.y) + (a3.z + a3.w))
            + ((a4.x + a4.y) + (a4.z + a4.w)) + ((a5.x + a5.y) + (a5.z + a5.w))
            + ((a6.x + a6.y) + (a6.z + a6.w)) + ((a7.x + a7.y) + (a7.z + a7.w));
    #pragma unroll
    for (int off = 16; off; off >>= 1)
        s += __shfl_down_sync(0xffffffffu, s, off);
    if (lane == 0) dst[row] = s;
}

// ---------------- K2: fused prep + per-batch contraction (64 blocks) -------
__global__ void contract_kernel(const float* __restrict__ E,
                                const float* __restrict__ R,
                                const float* __restrict__ U_root,
                                const float* __restrict__ P,
                                const float* __restrict__ gr, const float* __restrict__ br,
                                const float* __restrict__ ge, const float* __restrict__ be,
                                const int* __restrict__ r_idx,
                                const int* __restrict__ e2_idx,
                                const int* __restrict__ e3_idx,
                                const int* __restrict__ miss_p)
{
    int b = blockIdx.x, t = threadIdx.x;     // 256 threads
    int wid = t >> 5, lane = t & 31;
    int miss = miss_p ? *miss_p : 3;

    __shared__ float shr[2048], sh2[2048], sh3[2048];
    __shared__ int   idxs[192];              // [0:64) r, [64:128) e2, [128:192) e3
    __shared__ float Rn[32], E2n[32], E3n[32];
    __shared__ float A1s[32], A2s[32], Vs[32];
    __shared__ float m[1024];                // outer product A1⊗A2
    __shared__ float y[1024];                // coef[r]*V[j]
    __shared__ float afr[32];                // a[b][r] = U_root[ridx[b]][r].sum()
    __shared__ float p_sh[32];               // p[r] = P[r].sum()
    __shared__ float coef[32];
    __shared__ float partial[8][32];

    if (t < 64)        idxs[t]       = r_idx[t];
    else if (t < 128)  idxs[t]       = e2_idx[t - 64];
    else if (t < 192)  idxs[t]       = e3_idx[t - 128];
    __syncthreads();

    // gather all 64 rows of each (for BN stats)
    for (int i = t; i < 2048; i += 256) {
        int bb = i >> 5, d = i & 31;
        shr[i] = R[(size_t)idxs[bb] * 32 + d];
        sh2[i] = E[(size_t)idxs[64 + bb] * 32 + d];
        sh3[i] = E[(size_t)idxs[128 + bb] * 32 + d];
    }
    // warp 7: p[r] = P.sum(-1)
    if (wid == 7) {
        const float4* row = reinterpret_cast<const float4*>(P + lane * 32);
        float s = 0.f;
        #pragma unroll
        for (int q = 0; q < 8; q++) { float4 v = row[q]; s += (v.x+v.y)+(v.z+v.w); }
        p_sh[lane] = s;
    }
    // all threads: afr[r] = U_root[ridx[b]][r].sum(); thread (r=t>>3, seg=t&7)
    {
        int ridx = r_idx[b];
        const float4* seg = reinterpret_cast<const float4*>(
            U_root + ((size_t)ridx * 32 + (t >> 3)) * 32) + (t & 7);
        float4 v = *seg;
        float s = (v.x + v.y) + (v.z + v.w);
        s += __shfl_down_sync(0xffffffffu, s, 4, 8);
        s += __shfl_down_sync(0xffffffffu, s, 2, 8);
        s += __shfl_down_sync(0xffffffffu, s, 1, 8);
        if ((t & 7) == 0) afr[t >> 3] = s;
    }
    __syncthreads();

    // warps 0..2: BN stats for R / e2 / e3, normalize ONLY row b
    if (wid < 3) {
        const float* sh  = (wid == 0) ? shr : (wid == 1) ? sh2 : sh3;
        const float* gg  = (wid == 0) ? gr  : ge;
        const float* bb  = (wid == 0) ? br  : be;
        float* dst       = (wid == 0) ? Rn  : (wid == 1) ? E2n : E3n;
        float mm = 0.f;
        #pragma unroll 8
        for (int q = 0; q < 64; q++) mm += sh[q * 32 + lane];
        mm *= (1.f / 64.f);
        float var = 0.f;
        #pragma unroll 8
        for (int q = 0; q < 64; q++) { float d = sh[q * 32 + lane] - mm; var += d * d; }
        var *= (1.f / 64.f);
        float sc = gg[lane] * rsqrtf(var + EPS);
        float of = bb[lane] - mm * sc;
        dst[lane] = sh[b * 32 + lane] * sc + of;
    }
    __syncthreads();

    if (t < 32) {
        if (miss == 1) { A1s[t] = E2n[t]; A2s[t] = E3n[t]; Vs[t] = Rn[t]; }
        else           { A1s[t] = Rn[t];  A2s[t] = E2n[t]; Vs[t] = E3n[t]; }
    }
    __syncthreads();
    for (int i = t; i < 1024; i += 256) m[i] = A1s[i >> 5] * A2s[i & 31];
    __syncthreads();

    const float* SU = (miss == 1) ? g_u3red  : g_u12red;   // scalar side
    const float* TU = (miss == 1) ? g_u12red : g_u3red;    // vector side

    // coef[r] = (Σ_ii SU[r,ii]*m[ii]) * afr[r] * p[r]; warp wid owns r in [4w,4w+4)
    #pragma unroll
    for (int rr = 0; rr < 4; rr++) {
        int r = wid * 4 + rr;
        const float4* row = reinterpret_cast<const float4*>(SU + (size_t)r * 1024);
        float s = 0.f;
        #pragma unroll
        for (int q = 0; q < 8; q++) {
            float4 u = row[q * 32 + lane];
            const float4 mm = reinterpret_cast<const float4*>(m)[q * 32 + lane];
            s += u.x * mm.x + u.y * mm.y + u.z * mm.z + u.w * mm.w;
        }
        #pragma unroll
        for (int off = 16; off; off >>= 1)
            s += __shfl_down_sync(0xffffffffu, s, off);
        if (lane == 0) coef[r] = s * afr[r] * p_sh[r];
    }
    __syncthreads();
    for (int i = t; i < 1024; i += 256) y[i] = coef[i >> 5] * Vs[i & 31];
    __syncthreads();

    // output: thread (k=t&31, part=t>>5); part owns r in [4p,4p+4)
    int k = t & 31, part = t >> 5;
    float acc = 0.f;
    if (miss == 2) {
        #pragma unroll
        for (int rr = 0; rr < 4; rr++) {
            int r = part * 4 + rr;
            const float4* seg = reinterpret_cast<const float4*>(TU + (size_t)r * 1024 + k * 32);
            #pragma unroll
            for (int q = 0; q < 8; q++) {
                float4 u = seg[q];
                acc += u.x * y[r*32 + q*4]   + u.y * y[r*32 + q*4+1]
                     + u.z * y[r*32 + q*4+2] + u.w * y[r*32 + q*4+3];
            }
        }
    } else {
        #pragma unroll
        for (int rr = 0; rr < 4; rr++) {
            int r = part * 4 + rr;
            #pragma unroll
            for (int j = 0; j < 32; j++)
                acc += y[r * 32 + j] * TU[(size_t)r * 1024 + j * 32 + k];
        }
    }
    partial[part][k] = acc;
    __syncthreads();
    if (t < 32) {
        float s = 0.f;
        #pragma unroll
        for (int p8 = 0; p8 < 8; p8++) s += partial[p8][t];
        g_vec[b * 32 + t] = s;
    }
}

// ---------------- K3: logits + exp + per-block sums (BN(vec) inline) -------
// Grid (391, 2), block 128. blockIdx.y selects a 32-row b-half; each thread
// owns ONE entity (er in 32 regs) and loops over 32 b's in chunks of 4.
__global__ void logits_kernel(const float* __restrict__ E,
                              const float* __restrict__ gw,
                              const float* __restrict__ bw,
                              float* __restrict__ out)
{
    __shared__ float  vraw[2048];
    __shared__ float  pm[4][32];             // partial BN sums
    __shared__ float  sc_s[32], of_s[32], mean_s[32];
    __shared__ float4 vecn4[256];            // this half's BN'd vec: [32 b][8 q]
    __shared__ float  wsum[32][4];
    int t = threadIdx.x;                     // 128
    int bhalf = blockIdx.y;                  // 0 or 1
    {
        const float4* gv4 = reinterpret_cast<const float4*>(g_vec);
        float4* vr4 = reinterpret_cast<float4*>(vraw);
        for (int i = t; i < 512; i += 128) vr4[i] = gv4[i];
    }
    __syncthreads();

    // BN stats, parallel over all 128 threads: feature f = t&31, quarter = t>>5
    {
        int f = t & 31, qr = t >> 5;
        float s = 0.f;
        #pragma unroll
        for (int q = 0; q < 16; q++) s += vraw[(qr * 16 + q) * 32 + f];
        pm[qr][f] = s;
    }
    __syncthreads();
    if (t < 32) {
        float m = (pm[0][t] + pm[1][t]) + (pm[2][t] + pm[3][t]);
        mean_s[t] = m * (1.f / 64.f);
    }
    __syncthreads();
    {
        int f = t & 31, qr = t >> 5;
        float m = mean_s[f];
        float s = 0.f;
        #pragma unroll
        for (int q = 0; q < 16; q++) {
            float d = vraw[(qr * 16 + q) * 32 + f] - m;
            s += d * d;
        }
        pm[qr][f] = s;
    }
    __syncthreads();
    if (t < 32) {
        float var = ((pm[0][t] + pm[1][t]) + (pm[2][t] + pm[3][t])) * (1.f / 64.f);
        float sc = gw[t] * rsqrtf(var + EPS);
        sc_s[t] = sc;
        of_s[t] = bw[t] - mean_s[t] * sc;
    }
    __syncthreads();
    {
        float* vecnf = reinterpret_cast<float*>(vecn4);
        for (int i = t; i < 1024; i += 128) {
            int src = bhalf * 1024 + i;
            vecnf[i] = vraw[src] * sc_s[i & 31] + of_s[i & 31];
        }
    }
    __syncthreads();

    int n = blockIdx.x * 128 + t;
    bool valid = n < ENT;
    float4 er[8];
    if (valid) {
        const float4* p = reinterpret_cast<const float4*>(E + (size_t)n * 32);
        #pragma unroll
        for (int q = 0; q < 8; q++) er[q] = p[q];
    } else {
        #pragma unroll
        for (int q = 0; q < 8; q++) er[q] = make_float4(0.f, 0.f, 0.f, 0.f);
    }

    int wid = t >> 5, lane = t & 31;
    size_t outbase = (size_t)(bhalf * 32) * ENT + n;

    #pragma unroll
    for (int c = 0; c < 8; c++) {            // 8 chunks of 4 b's
        int bl = c * 4;
        float l0 = 0.f, l1 = 0.f, l2 = 0.f, l3 = 0.f;
        #pragma unroll
        for (int q = 0; q < 8; q++) {
            float4 e  = er[q];
            float4 w0 = vecn4[(bl + 0) * 8 + q];
            float4 w1 = vecn4[(bl + 1) * 8 + q];
            float4 w2 = vecn4[(bl + 2) * 8 + q];
            float4 w3 = vecn4[(bl + 3) * 8 + q];
            l0 += w0.x*e.x + w0.y*e.y + w0.z*e.z + w0.w*e.w;
            l1 += w1.x*e.x + w1.y*e.y + w1.z*e.z + w1.w*e.w;
            l2 += w2.x*e.x + w2.y*e.y + w2.z*e.z + w2.w*e.w;
            l3 += w3.x*e.x + w3.y*e.y + w3.z*e.z + w3.w*e.w;
        }
        float p0 = valid ? exp_small(l0) : 0.f;
        float p1 = valid ? exp_small(l1) : 0.f;
        float p2 = valid ? exp_small(l2) : 0.f;
        float p3 = valid ? exp_small(l3) : 0.f;
        if (valid) {
            out[outbase + (size_t)(bl + 0) * ENT] = p0;
            out[outbase + (size_t)(bl + 1) * ENT] = p1;
            out[outbase + (size_t)(bl + 2) * ENT] = p2;
            out[outbase + (size_t)(bl + 3) * ENT] = p3;
        }
        #pragma unroll
        for (int off = 16; off; off >>= 1) {
            p0 += __shfl_down_sync(0xffffffffu, p0, off);
            p1 += __shfl_down_sync(0xffffffffu, p1, off);
            p2 += __shfl_down_sync(0xffffffffu, p2, off);
            p3 += __shfl_down_sync(0xffffffffu, p3, off);
        }
        if (lane == 0) {
            wsum[bl + 0][wid] = p0; wsum[bl + 1][wid] = p1;
            wsum[bl + 2][wid] = p2; wsum[bl + 3][wid] = p3;
        }
    }
    __syncthreads();
    if (t < 32)                              // transposed: [b][blk], coalesced for norm
        g_bsum[(size_t)(bhalf * 32 + t) * 512 + blockIdx.x] =
            (wsum[t][0] + wsum[t][1]) + (wsum[t][2] + wsum[t][3]);
}

// ---------------- K4: normalize ---------------------------------------------
// Grid (7, 64), 256 threads, 8 float4 per thread. Denominator reduce:
// warp shuffles + single 8-value combine (2 barriers only).
__global__ void norm_kernel(float* __restrict__ out, int nblk)
{
    __shared__ float wred[8];
    int b = blockIdx.y, t = threadIdx.x;
    int wid = t >> 5, lane = t & 31;
    float s = 0.f;
    {
        const float* row = g_bsum + (size_t)b * 512;
        if (t < nblk) s = row[t];
        int t2 = t + 256;
        if (t2 < nblk) s += row[t2];
    }
    #pragma unroll
    for (int off = 16; off; off >>= 1)
        s += __shfl_down_sync(0xffffffffu, s, off);
    if (lane == 0) wred[wid] = s;
    __syncthreads();
    float tot = ((wred[0] + wred[1]) + (wred[2] + wred[3]))
              + ((wred[4] + wred[5]) + (wred[6] + wred[7]));
    float inv = 1.f / tot;

    float4* p = reinterpret_cast<float4*>(out + (size_t)b * ENT);
    int base = blockIdx.x * 2048 + t;        // float4 index (12500 per row)
    #pragma unroll
    for (int u = 0; u < 8; u++) {
        int i = base + u * 256;
        if (i < 12500) {
            float4 v = p[i];
            v.x *= inv; v.y *= inv; v.z *= inv; v.w *= inv;
            p[i] = v;
        }
    }
}

// ---------------- launch ----------------------------------------------------
extern "C" void kernel_launch(void* const* d_in, const int* in_sizes, int n_in,
                              void* d_out, int out_size)
{
    const float* E      = (const float*)d_in[0];
    const float* R      = (const float*)d_in[1];
    const float* U_root = (const float*)d_in[2];
    const float* U12    = (const float*)d_in[3];
    const float* U3R    = (const float*)d_in[4];
    const float* P      = (const float*)d_in[5];
    const float* gr     = (const float*)d_in[6];
    const float* br     = (const float*)d_in[7];
    const float* ge     = (const float*)d_in[8];
    const float* be     = (const float*)d_in[9];
    const float* gw     = (const float*)d_in[10];
    const float* bw     = (const float*)d_in[11];
    const int* r_idx    = (const int*)d_in[12];
    const int* e2_idx   = (const int*)d_in[13];
    const int* e3_idx   = (const int*)d_in[14];
    const int* miss     = (n_in > 15) ? (const int*)d_in[15] : nullptr;
    float* out = (float*)d_out;

    reduce_kernel<<<8192, 256>>>(U12, U3R);
    contract_kernel<<<64, 256>>>(E, R, U_root, P, gr, br, ge, be,
                                 r_idx, e2_idx, e3_idx, miss);
    logits_kernel<<<dim3(LOG_BLKS, 2), 128>>>(E, gw, bw, out);
    norm_kernel<<<dim3(7, 64), 256>>>(out, LOG_BLKS);
}

// round 13
// speedup vs baseline: 1.3173x; 1.1340x over previous
#include <cuda_runtime.h>
#include <cstdint>

#define EPS 1e-5f

// ---------------- scratch (device globals; allocation-free) ----------------
__device__ float g_u12red[32 * 1024];       // [r, ii]  sum over last axis of U12
__device__ float g_u3red [32 * 1024];       // [r, jj]  sum over last axis of U3R
__device__ float g_vec [64 * 32];           // vec (pre-BN)
__device__ float g_bsum[64 * 512];          // per-b, per-logit-block exp partials (TRANSPOSED)
__device__ float g_inv [64];                // 1 / softmax denominator per b

static const int ENT = 50000;
static const int LOG_BLKS = (ENT + 127) / 128;   // 391 (128 entities per block)

// exp(x) for small |x| via degree-6 Taylor (pure FFMA, no MUFU).
// Logits here are |x| <~ 0.04 by construction; fallback for safety.
__device__ __forceinline__ float exp_small(float x)
{
    if (fabsf(x) > 0.6f) return __expf(x);   // never taken in practice
    float p = 1.388888889e-3f;               // 1/720
    p = fmaf(p, x, 8.333333333e-3f);         // 1/120
    p = fmaf(p, x, 4.166666667e-2f);         // 1/24
    p = fmaf(p, x, 1.666666667e-1f);         // 1/6
    p = fmaf(p, x, 0.5f);
    p = fmaf(p, x, 1.0f);
    p = fmaf(p, x, 1.0f);
    return p;
}

// ---------------- K1: row reduction of U12 and U3R (the 256 MB stream) -----
__global__ void reduce_kernel(const float* __restrict__ U12,
                              const float* __restrict__ U3R)
{
    int gw   = (blockIdx.x * 256 + threadIdx.x) >> 5;   // global warp id, 65536 total
    int lane = threadIdx.x & 31;
    const float* src;
    float* dst;
    int row;
    if (gw < 32768) { src = U12; dst = g_u12red; row = gw; }
    else            { src = U3R; dst = g_u3red;  row = gw - 32768; }

    const float4* p = reinterpret_cast<const float4*>(src + (size_t)row * 1024) + lane;
    float4 a0 = __ldcs(p +   0), a1 = __ldcs(p +  32);
    float4 a2 = __ldcs(p +  64), a3 = __ldcs(p +  96);
    float4 a4 = __ldcs(p + 128), a5 = __ldcs(p + 160);
    float4 a6 = __ldcs(p + 192), a7 = __ldcs(p + 224);
    float s = ((a0.x + a0.y) + (a0.z + a0.w)) + ((a1.x + a1.y) + (a1.z + a1.w))
            + ((a2.x + a2.y) + (a2.z + a2.w)) + ((a3.x + a3.y) + (a3.z + a3.w))
            + ((a4.x + a4.y) + (a4.z + a4.w)) + ((a5.x + a5.y) + (a5.z + a5.w))
            + ((a6.x + a6.y) + (a6.z + a6.w)) + ((a7.x + a7.y) + (a7.z + a7.w));
    #pragma unroll
    for (int off = 16; off; off >>= 1)
        s += __shfl_down_sync(0xffffffffu, s, off);
    if (lane == 0) dst[row] = s;
}

// ---------------- K2: fused prep + per-batch contraction (64 blocks) -------
__global__ void contract_kernel(const float* __restrict__ E,
                                const float* __restrict__ R,
                                const float* __restrict__ U_root,
                                const float* __restrict__ P,
                                const float* __restrict__ gr, const float* __restrict__ br,
                                const float* __restrict__ ge, const float* __restrict__ be,
                                const int* __restrict__ r_idx,
                                const int* __restrict__ e2_idx,
                                const int* __restrict__ e3_idx,
                                const int* __restrict__ miss_p)
{
    int b = blockIdx.x, t = threadIdx.x;     // 256 threads
    int wid = t >> 5, lane = t & 31;
    int miss = miss_p ? *miss_p : 3;

    __shared__ float shr[2048], sh2[2048], sh3[2048];
    __shared__ int   idxs[192];              // [0:64) r, [64:128) e2, [128:192) e3
    __shared__ float Rn[32], E2n[32], E3n[32];
    __shared__ float A1s[32], A2s[32], Vs[32];
    __shared__ float m[1024];                // outer product A1⊗A2
    __shared__ float y[1024];                // coef[r]*V[j]
    __shared__ float afr[32];                // a[b][r] = U_root[ridx[b]][r].sum()
    __shared__ float p_sh[32];               // p[r] = P[r].sum()
    __shared__ float coef[32];
    __shared__ float partial[8][32];

    if (t < 64)        idxs[t]       = r_idx[t];
    else if (t < 128)  idxs[t]       = e2_idx[t - 64];
    else if (t < 192)  idxs[t]       = e3_idx[t - 128];
    __syncthreads();

    // gather all 64 rows of each (for BN stats)
    for (int i = t; i < 2048; i += 256) {
        int bb = i >> 5, d = i & 31;
        shr[i] = R[(size_t)idxs[bb] * 32 + d];
        sh2[i] = E[(size_t)idxs[64 + bb] * 32 + d];
        sh3[i] = E[(size_t)idxs[128 + bb] * 32 + d];
    }
    // warp 7: p[r] = P.sum(-1)
    if (wid == 7) {
        const float4* row = reinterpret_cast<const float4*>(P + lane * 32);
        float s = 0.f;
        #pragma unroll
        for (int q = 0; q < 8; q++) { float4 v = row[q]; s += (v.x+v.y)+(v.z+v.w); }
        p_sh[lane] = s;
    }
    // all threads: afr[r] = U_root[ridx[b]][r].sum(); thread (r=t>>3, seg=t&7)
    {
        int ridx = r_idx[b];
        const float4* seg = reinterpret_cast<const float4*>(
            U_root + ((size_t)ridx * 32 + (t >> 3)) * 32) + (t & 7);
        float4 v = *seg;
        float s = (v.x + v.y) + (v.z + v.w);
        s += __shfl_down_sync(0xffffffffu, s, 4, 8);
        s += __shfl_down_sync(0xffffffffu, s, 2, 8);
        s += __shfl_down_sync(0xffffffffu, s, 1, 8);
        if ((t & 7) == 0) afr[t >> 3] = s;
    }
    __syncthreads();

    // warps 0..2: BN stats for R / e2 / e3, normalize ONLY row b
    if (wid < 3) {
        const float* sh  = (wid == 0) ? shr : (wid == 1) ? sh2 : sh3;
        const float* gg  = (wid == 0) ? gr  : ge;
        const float* bb  = (wid == 0) ? br  : be;
        float* dst       = (wid == 0) ? Rn  : (wid == 1) ? E2n : E3n;
        float mm = 0.f;
        #pragma unroll 8
        for (int q = 0; q < 64; q++) mm += sh[q * 32 + lane];
        mm *= (1.f / 64.f);
        float var = 0.f;
        #pragma unroll 8
        for (int q = 0; q < 64; q++) { float d = sh[q * 32 + lane] - mm; var += d * d; }
        var *= (1.f / 64.f);
        float sc = gg[lane] * rsqrtf(var + EPS);
        float of = bb[lane] - mm * sc;
        dst[lane] = sh[b * 32 + lane] * sc + of;
    }
    __syncthreads();

    if (t < 32) {
        if (miss == 1) { A1s[t] = E2n[t]; A2s[t] = E3n[t]; Vs[t] = Rn[t]; }
        else           { A1s[t] = Rn[t];  A2s[t] = E2n[t]; Vs[t] = E3n[t]; }
    }
    __syncthreads();
    for (int i = t; i < 1024; i += 256) m[i] = A1s[i >> 5] * A2s[i & 31];
    __syncthreads();

    const float* SU = (miss == 1) ? g_u3red  : g_u12red;   // scalar side
    const float* TU = (miss == 1) ? g_u12red : g_u3red;    // vector side

    // coef[r] = (Σ_ii SU[r,ii]*m[ii]) * afr[r] * p[r]; warp wid owns r in [4w,4w+4)
    #pragma unroll
    for (int rr = 0; rr < 4; rr++) {
        int r = wid * 4 + rr;
        const float4* row = reinterpret_cast<const float4*>(SU + (size_t)r * 1024);
        float s = 0.f;
        #pragma unroll
        for (int q = 0; q < 8; q++) {
            float4 u = row[q * 32 + lane];
            const float4 mm = reinterpret_cast<const float4*>(m)[q * 32 + lane];
            s += u.x * mm.x + u.y * mm.y + u.z * mm.z + u.w * mm.w;
        }
        #pragma unroll
        for (int off = 16; off; off >>= 1)
            s += __shfl_down_sync(0xffffffffu, s, off);
        if (lane == 0) coef[r] = s * afr[r] * p_sh[r];
    }
    __syncthreads();
    for (int i = t; i < 1024; i += 256) y[i] = coef[i >> 5] * Vs[i & 31];
    __syncthreads();

    // output: thread (k=t&31, part=t>>5); part owns r in [4p,4p+4)
    int k = t & 31, part = t >> 5;
    float acc = 0.f;
    if (miss == 2) {
        #pragma unroll
        for (int rr = 0; rr < 4; rr++) {
            int r = part * 4 + rr;
            const float4* seg = reinterpret_cast<const float4*>(TU + (size_t)r * 1024 + k * 32);
            #pragma unroll
            for (int q = 0; q < 8; q++) {
                float4 u = seg[q];
                acc += u.x * y[r*32 + q*4]   + u.y * y[r*32 + q*4+1]
                     + u.z * y[r*32 + q*4+2] + u.w * y[r*32 + q*4+3];
            }
        }
    } else {
        #pragma unroll
        for (int rr = 0; rr < 4; rr++) {
            int r = part * 4 + rr;
            #pragma unroll
            for (int j = 0; j < 32; j++)
                acc += y[r * 32 + j] * TU[(size_t)r * 1024 + j * 32 + k];
        }
    }
    partial[part][k] = acc;
    __syncthreads();
    if (t < 32) {
        float s = 0.f;
        #pragma unroll
        for (int p8 = 0; p8 < 8; p8++) s += partial[p8][t];
        g_vec[b * 32 + t] = s;
    }
}

// ---------------- K3: logits + exp + per-block sums (BN(vec) inline) -------
// Grid (391, 2), block 128. blockIdx.y selects a 32-row b-half; each thread
// owns ONE entity (er in 32 regs) and loops over 32 b's in chunks of 4.
__global__ void logits_kernel(const float* __restrict__ E,
                              const float* __restrict__ gw,
                              const float* __restrict__ bw,
                              float* __restrict__ out)
{
    __shared__ float  vraw[2048];
    __shared__ float  pm[4][32];             // partial BN sums
    __shared__ float  sc_s[32], of_s[32], mean_s[32];
    __shared__ float4 vecn4[256];            // this half's BN'd vec: [32 b][8 q]
    __shared__ float  wsum[32][4];
    int t = threadIdx.x;                     // 128
    int bhalf = blockIdx.y;                  // 0 or 1
    {
        const float4* gv4 = reinterpret_cast<const float4*>(g_vec);
        float4* vr4 = reinterpret_cast<float4*>(vraw);
        for (int i = t; i < 512; i += 128) vr4[i] = gv4[i];
    }
    __syncthreads();

    // BN stats, parallel over all 128 threads: feature f = t&31, quarter = t>>5
    {
        int f = t & 31, qr = t >> 5;
        float s = 0.f;
        #pragma unroll
        for (int q = 0; q < 16; q++) s += vraw[(qr * 16 + q) * 32 + f];
        pm[qr][f] = s;
    }
    __syncthreads();
    if (t < 32) {
        float m = (pm[0][t] + pm[1][t]) + (pm[2][t] + pm[3][t]);
        mean_s[t] = m * (1.f / 64.f);
    }
    __syncthreads();
    {
        int f = t & 31, qr = t >> 5;
        float m = mean_s[f];
        float s = 0.f;
        #pragma unroll
        for (int q = 0; q < 16; q++) {
            float d = vraw[(qr * 16 + q) * 32 + f] - m;
            s += d * d;
        }
        pm[qr][f] = s;
    }
    __syncthreads();
    if (t < 32) {
        float var = ((pm[0][t] + pm[1][t]) + (pm[2][t] + pm[3][t])) * (1.f / 64.f);
        float sc = gw[t] * rsqrtf(var + EPS);
        sc_s[t] = sc;
        of_s[t] = bw[t] - mean_s[t] * sc;
    }
    __syncthreads();
    {
        float* vecnf = reinterpret_cast<float*>(vecn4);
        for (int i = t; i < 1024; i += 128) {
            int src = bhalf * 1024 + i;
            vecnf[i] = vraw[src] * sc_s[i & 31] + of_s[i & 31];
        }
    }
    __syncthreads();

    int n = blockIdx.x * 128 + t;
    bool valid = n < ENT;
    float4 er[8];
    if (valid) {
        const float4* p = reinterpret_cast<const float4*>(E + (size_t)n * 32);
        #pragma unroll
        for (int q = 0; q < 8; q++) er[q] = p[q];
    } else {
        #pragma unroll
        for (int q = 0; q < 8; q++) er[q] = make_float4(0.f, 0.f, 0.f, 0.f);
    }

    int wid = t >> 5, lane = t & 31;
    size_t outbase = (size_t)(bhalf * 32) * ENT + n;

    #pragma unroll
    for (int c = 0; c < 8; c++) {            // 8 chunks of 4 b's
        int bl = c * 4;
        float l0 = 0.f, l1 = 0.f, l2 = 0.f, l3 = 0.f;
        #pragma unroll
        for (int q = 0; q < 8; q++) {
            float4 e  = er[q];
            float4 w0 = vecn4[(bl + 0) * 8 + q];
            float4 w1 = vecn4[(bl + 1) * 8 + q];
            float4 w2 = vecn4[(bl + 2) * 8 + q];
            float4 w3 = vecn4[(bl + 3) * 8 + q];
            l0 += w0.x*e.x + w0.y*e.y + w0.z*e.z + w0.w*e.w;
            l1 += w1.x*e.x + w1.y*e.y + w1.z*e.z + w1.w*e.w;
            l2 += w2.x*e.x + w2.y*e.y + w2.z*e.z + w2.w*e.w;
            l3 += w3.x*e.x + w3.y*e.y + w3.z*e.z + w3.w*e.w;
        }
        float p0 = valid ? exp_small(l0) : 0.f;
        float p1 = valid ? exp_small(l1) : 0.f;
        float p2 = valid ? exp_small(l2) : 0.f;
        float p3 = valid ? exp_small(l3) : 0.f;
        if (valid) {
            out[outbase + (size_t)(bl + 0) * ENT] = p0;
            out[outbase + (size_t)(bl + 1) * ENT] = p1;
            out[outbase + (size_t)(bl + 2) * ENT] = p2;
            out[outbase + (size_t)(bl + 3) * ENT] = p3;
        }
        #pragma unroll
        for (int off = 16; off; off >>= 1) {
            p0 += __shfl_down_sync(0xffffffffu, p0, off);
            p1 += __shfl_down_sync(0xffffffffu, p1, off);
            p2 += __shfl_down_sync(0xffffffffu, p2, off);
            p3 += __shfl_down_sync(0xffffffffu, p3, off);
        }
        if (lane == 0) {
            wsum[bl + 0][wid] = p0; wsum[bl + 1][wid] = p1;
            wsum[bl + 2][wid] = p2; wsum[bl + 3][wid] = p3;
        }
    }
    __syncthreads();
    if (t < 32)                              // transposed: [b][blk], coalesced for norm
        g_bsum[(size_t)(bhalf * 32 + t) * 512 + blockIdx.x] =
            (wsum[t][0] + wsum[t][1]) + (wsum[t][2] + wsum[t][3]);
}

// ---------------- K4: denominators (64 blocks, one per b) -------------------
__global__ void denom_kernel(int nblk)
{
    __shared__ float wred[4];
    int b = blockIdx.x, t = threadIdx.x;     // 128 threads
    int wid = t >> 5, lane = t & 31;
    const float* row = g_bsum + (size_t)b * 512;
    float s = 0.f;
    #pragma unroll
    for (int u = 0; u < 4; u++) {
        int q = t + u * 128;
        if (q < nblk) s += row[q];
    }
    #pragma unroll
    for (int off = 16; off; off >>= 1)
        s += __shfl_down_sync(0xffffffffu, s, off);
    if (lane == 0) wred[wid] = s;
    __syncthreads();
    if (t == 0)
        g_inv[b] = 1.f / ((wred[0] + wred[1]) + (wred[2] + wred[3]));
}

// ---------------- K5: normalize (pure streaming scale) ----------------------
// Grid (25, 64), 256 threads, 2 float4 per thread; no barriers, no reduction.
__global__ void norm_kernel(float* __restrict__ out)
{
    int b = blockIdx.y, t = threadIdx.x;
    float inv = g_inv[b];
    float4* p = reinterpret_cast<float4*>(out + (size_t)b * ENT);
    int base = blockIdx.x * 512 + t;         // float4 index (12500 per row)
    #pragma unroll
    for (int u = 0; u < 2; u++) {
        int i = base + u * 256;
        if (i < 12500) {
            float4 v = p[i];
            v.x *= inv; v.y *= inv; v.z *= inv; v.w *= inv;
            p[i] = v;
        }
    }
}

// ---------------- launch ----------------------------------------------------
extern "C" void kernel_launch(void* const* d_in, const int* in_sizes, int n_in,
                              void* d_out, int out_size)
{
    const float* E      = (const float*)d_in[0];
    const float* R      = (const float*)d_in[1];
    const float* U_root = (const float*)d_in[2];
    const float* U12    = (const float*)d_in[3];
    const float* U3R    = (const float*)d_in[4];
    const float* P      = (const float*)d_in[5];
    const float* gr     = (const float*)d_in[6];
    const float* br     = (const float*)d_in[7];
    const float* ge     = (const float*)d_in[8];
    const float* be     = (const float*)d_in[9];
    const float* gw     = (const float*)d_in[10];
    const float* bw     = (const float*)d_in[11];
    const int* r_idx    = (const int*)d_in[12];
    const int* e2_idx   = (const int*)d_in[13];
    const int* e3_idx   = (const int*)d_in[14];
    const int* miss     = (n_in > 15) ? (const int*)d_in[15] : nullptr;
    float* out = (float*)d_out;

    reduce_kernel<<<8192, 256>>>(U12, U3R);
    contract_kernel<<<64, 256>>>(E, R, U_root, P, gr, br, ge, be,
                                 r_idx, e2_idx, e3_idx, miss);
    logits_kernel<<<dim3(LOG_BLKS, 2), 128>>>(E, gw, bw, out);
    denom_kernel<<<64, 128>>>(LOG_BLKS);
    norm_kernel<<<dim3(25, 64), 256>>>(out);
}